// round 2
// baseline (speedup 1.0000x reference)
#include <cuda_runtime.h>

#define BSZ   4096
#define DIM   1024
#define NC    100
#define NCP   128
#define NITER 30
#define NLAB  2048

// ---- scratch (static device globals; no runtime allocation) ----
__device__ float g_ne[(size_t)BSZ * DIM];        // normalized embeddings (16 MB)
__device__ float g_A[(size_t)BSZ * BSZ];         // affinity matrix (64 MB)
__device__ float g_X[2][(size_t)BSZ * NCP];      // double-buffered X, padded to 128 cols
__device__ float g_part[1024];
__device__ float g_mean;

// ---- f32x2 helpers (sm_103a packed fp32 FMA) ----
__device__ __forceinline__ unsigned long long bcast2(float x) {
    unsigned long long r;
    asm("mov.b64 %0, {%1, %1};" : "=l"(r) : "f"(x));
    return r;
}
__device__ __forceinline__ void ffma2(unsigned long long& d, unsigned long long a, unsigned long long b) {
    asm("fma.rn.f32x2 %0, %1, %2, %0;" : "+l"(d) : "l"(a), "l"(b));
}
__device__ __forceinline__ float lo2(unsigned long long v) { return __uint_as_float((unsigned)v); }
__device__ __forceinline__ float hi2(unsigned long long v) { return __uint_as_float((unsigned)(v >> 32)); }

// ---- K1: row-normalize embeddings ----
__global__ void k_normalize(const float* __restrict__ emb) {
    int r = blockIdx.x;
    int tid = threadIdx.x;                       // 256 threads, 4 floats each
    float4 x = ((const float4*)(emb + (size_t)r * DIM))[tid];
    float ss = x.x * x.x + x.y * x.y + x.z * x.z + x.w * x.w;
    __shared__ float red[8];
#pragma unroll
    for (int o = 16; o; o >>= 1) ss += __shfl_xor_sync(0xffffffffu, ss, o);
    if ((tid & 31) == 0) red[tid >> 5] = ss;
    __syncthreads();
    float tot = red[0] + red[1] + red[2] + red[3] + red[4] + red[5] + red[6] + red[7];
    float sc = 1.f / (sqrtf(tot) + 1e-12f);
    x.x *= sc; x.y *= sc; x.z *= sc; x.w *= sc;
    ((float4*)(g_ne + (size_t)r * DIM))[tid] = x;
}

// ---- K2: A = clamp(ne @ ne^T, 0, 1), diag = 0 ; symmetric (mirror writes) ----
#define TM2 128
#define TN2 64
#define TK2 16
#define ATLD 132
#define BSLD 68
#define CSLD 69

__global__ void __launch_bounds__(256) k_gemmA() {
    __shared__ __align__(16) float sm[TM2 * CSLD];   // 8832 floats, overlaid usage
    float* At = sm;                                   // [TK2][ATLD] transposed A tile
    float* Bs = sm + TK2 * ATLD;                      // [TK2][BSLD] transposed B tile
    int r0 = blockIdx.y * TM2;
    int c0 = blockIdx.x * TN2;
    if (c0 + TN2 <= r0) return;                       // fully below diagonal: covered by mirror
    int tid = threadIdx.x;
    int tx = tid & 15, ty = tid >> 4;
    int m0 = ty * 8, n0 = tx * 4;
    unsigned long long acc[4][4];
#pragma unroll
    for (int p = 0; p < 4; p++)
#pragma unroll
        for (int n = 0; n < 4; n++) acc[p][n] = 0ULL;

    for (int k0 = 0; k0 < DIM; k0 += TK2) {
        __syncthreads();
#pragma unroll
        for (int i = 0; i < 2; i++) {
            int s = tid + i * 256;
            int r = s >> 2, q = (s & 3) * 4;
            float4 v = *(const float4*)(g_ne + (size_t)(r0 + r) * DIM + k0 + q);
            At[(q + 0) * ATLD + r] = v.x;
            At[(q + 1) * ATLD + r] = v.y;
            At[(q + 2) * ATLD + r] = v.z;
            At[(q + 3) * ATLD + r] = v.w;
        }
        {
            int r = tid >> 2, q = (tid & 3) * 4;
            float4 v = *(const float4*)(g_ne + (size_t)(c0 + r) * DIM + k0 + q);
            Bs[(q + 0) * BSLD + r] = v.x;
            Bs[(q + 1) * BSLD + r] = v.y;
            Bs[(q + 2) * BSLD + r] = v.z;
            Bs[(q + 3) * BSLD + r] = v.w;
        }
        __syncthreads();
#pragma unroll
        for (int k = 0; k < TK2; k++) {
            ulonglong2 aA = *(const ulonglong2*)(At + k * ATLD + m0);
            ulonglong2 aB = *(const ulonglong2*)(At + k * ATLD + m0 + 4);
            float4 bv = *(const float4*)(Bs + k * BSLD + n0);
            unsigned long long b0 = bcast2(bv.x), b1 = bcast2(bv.y);
            unsigned long long b2 = bcast2(bv.z), b3 = bcast2(bv.w);
            ffma2(acc[0][0], aA.x, b0); ffma2(acc[0][1], aA.x, b1);
            ffma2(acc[0][2], aA.x, b2); ffma2(acc[0][3], aA.x, b3);
            ffma2(acc[1][0], aA.y, b0); ffma2(acc[1][1], aA.y, b1);
            ffma2(acc[1][2], aA.y, b2); ffma2(acc[1][3], aA.y, b3);
            ffma2(acc[2][0], aB.x, b0); ffma2(acc[2][1], aB.x, b1);
            ffma2(acc[2][2], aB.x, b2); ffma2(acc[2][3], aB.x, b3);
            ffma2(acc[3][0], aB.y, b0); ffma2(acc[3][1], aB.y, b1);
            ffma2(acc[3][2], aB.y, b2); ffma2(acc[3][3], aB.y, b3);
        }
    }
    __syncthreads();
#pragma unroll
    for (int p = 0; p < 4; p++)
#pragma unroll
        for (int n = 0; n < 4; n++) {
            sm[(m0 + 2 * p) * CSLD + n0 + n]     = lo2(acc[p][n]);
            sm[(m0 + 2 * p + 1) * CSLD + n0 + n] = hi2(acc[p][n]);
        }
    __syncthreads();
    // direct write (coalesced)
    for (int idx = tid; idx < TM2 * TN2; idx += 256) {
        int i = idx >> 6, j = idx & 63;
        int gi = r0 + i, gj = c0 + j;
        float v = sm[i * CSLD + j];
        v = (gi == gj) ? 0.f : fminf(fmaxf(v, 0.f), 1.f);
        g_A[(size_t)gi * BSZ + gj] = v;
    }
    // mirror write (coalesced along gi)
    for (int idx = tid; idx < TM2 * TN2; idx += 256) {
        int jj = idx >> 7, ii = idx & 127;
        int gi = r0 + ii, gj = c0 + jj;
        float v = sm[ii * CSLD + jj];
        v = (gi == gj) ? 0.f : fminf(fmaxf(v, 0.f), 1.f);
        g_A[(size_t)gj * BSZ + gi] = v;
    }
}

// ---- K3: deterministic mean of A (two-stage, no atomics) ----
__global__ void k_mean1() {
    int tid = threadIdx.x;
    size_t base = (size_t)blockIdx.x * 4096 + tid;   // float4 units
    const float4* A4 = (const float4*)g_A;
    float s = 0.f;
#pragma unroll
    for (int i = 0; i < 16; i++) {
        float4 v = A4[base + (size_t)i * 256];
        s += (v.x + v.y) + (v.z + v.w);
    }
    __shared__ float red[8];
#pragma unroll
    for (int o = 16; o; o >>= 1) s += __shfl_xor_sync(0xffffffffu, s, o);
    if ((tid & 31) == 0) red[tid >> 5] = s;
    __syncthreads();
    if (tid == 0) {
        float t = 0.f;
#pragma unroll
        for (int i = 0; i < 8; i++) t += red[i];
        g_part[blockIdx.x] = t;
    }
}

__global__ void k_mean2() {
    __shared__ float red[1024];
    int tid = threadIdx.x;
    red[tid] = g_part[tid];
    __syncthreads();
    for (int o = 512; o; o >>= 1) {
        if (tid < o) red[tid] += red[tid + o];
        __syncthreads();
    }
    if (tid == 0) g_mean = red[0] * (1.f / ((float)BSZ * (float)BSZ));
}

// ---- K4: threshold A below mean ----
__global__ void k_threshold() {
    float m = g_mean;
    size_t i = (size_t)blockIdx.x * 256 + threadIdx.x;
    float4* A4 = (float4*)g_A;
#pragma unroll
    for (int j = 0; j < 4; j++) {
        float4 v = A4[i + (size_t)j * 1048576];
        v.x = (v.x < m) ? 0.f : v.x;
        v.y = (v.y < m) ? 0.f : v.y;
        v.z = (v.z < m) ? 0.f : v.z;
        v.w = (v.w < m) ? 0.f : v.w;
        A4[i + (size_t)j * 1048576] = v;
    }
}

// ---- K5: init X (one-hot labelled, uniform unlabelled; padded cols zero) ----
// NOTE: labels are int32 (JAX downcasts int64 -> int32 with x64 disabled).
__global__ void k_initX(const int* __restrict__ labels) {
    int r = blockIdx.x, c = threadIdx.x;
    float v;
    if (r < NLAB) v = (c == labels[r]) ? 1.f : 0.f;
    else          v = (c < NC) ? 0.01f : 0.f;
    g_X[0][(size_t)r * NCP + c] = v;
}

// ---- K6: one replicator iteration: AX GEMM + div/entropy/output/X-update ----
#define TMI 32
#define TKI 32
#define IATLD 36
#define IXLD 132

__global__ void __launch_bounds__(256) k_iter(int t, float* __restrict__ outXs,
                                              float* __restrict__ outEnt) {
    const float* __restrict__ Xin = g_X[t & 1];
    float* __restrict__ Xout = g_X[(t + 1) & 1];
    __shared__ __align__(16) float sm[TKI * IATLD + TKI * IXLD];  // 5376 floats
    float* At = sm;                    // [TKI][IATLD] transposed A tile
    float* Xs = sm + TKI * IATLD;      // [TKI][IXLD] X tile
    float* Cs = sm;                    // overlay for epilogue, [TMI][IXLD]
    int r0 = blockIdx.x * TMI;
    int tid = threadIdx.x;
    int tx = tid & 15, ty = tid >> 4;
    int m0 = ty * 2, n0 = tx * 8;
    unsigned long long acc[2][4];
#pragma unroll
    for (int p = 0; p < 2; p++)
#pragma unroll
        for (int n = 0; n < 4; n++) acc[p][n] = 0ULL;

    for (int k0 = 0; k0 < BSZ; k0 += TKI) {
        __syncthreads();
        {
            int r = tid >> 3, q = (tid & 7) * 4;
            float4 v = *(const float4*)(g_A + (size_t)(r0 + r) * BSZ + k0 + q);
            At[(q + 0) * IATLD + r] = v.x;
            At[(q + 1) * IATLD + r] = v.y;
            At[(q + 2) * IATLD + r] = v.z;
            At[(q + 3) * IATLD + r] = v.w;
        }
#pragma unroll
        for (int i = 0; i < 4; i++) {
            int s = tid + i * 256;
            int kr = s >> 5, q = (s & 31) * 4;
            *(float4*)(Xs + kr * IXLD + q) =
                *(const float4*)(Xin + (size_t)(k0 + kr) * NCP + q);
        }
        __syncthreads();
#pragma unroll
        for (int k = 0; k < TKI; k++) {
            float2 av = *(const float2*)(At + k * IATLD + m0);
            unsigned long long a0 = bcast2(av.x), a1 = bcast2(av.y);
            ulonglong2 xA = *(const ulonglong2*)(Xs + k * IXLD + n0);
            ulonglong2 xB = *(const ulonglong2*)(Xs + k * IXLD + n0 + 4);
            ffma2(acc[0][0], a0, xA.x); ffma2(acc[0][1], a0, xA.y);
            ffma2(acc[0][2], a0, xB.x); ffma2(acc[0][3], a0, xB.y);
            ffma2(acc[1][0], a1, xA.x); ffma2(acc[1][1], a1, xA.y);
            ffma2(acc[1][2], a1, xB.x); ffma2(acc[1][3], a1, xB.y);
        }
    }
    __syncthreads();
#pragma unroll
    for (int rr = 0; rr < 2; rr++)
#pragma unroll
        for (int u = 0; u < 4; u++) {
            Cs[(m0 + rr) * IXLD + n0 + 2 * u]     = lo2(acc[rr][u]);
            Cs[(m0 + rr) * IXLD + n0 + 2 * u + 1] = hi2(acc[rr][u]);
        }
    __syncthreads();

    int warp = tid >> 5, lane = tid & 31;
    for (int rr = warp; rr < TMI; rr += 8) {
        int gr = r0 + rr;
        float nums[4];
        float ssum = 0.f;
#pragma unroll
        for (int it = 0; it < 4; it++) {
            int c = lane + it * 32;
            float num = 0.f;
            if (c < NC) num = Xin[(size_t)gr * NCP + c] * Cs[rr * IXLD + c];
            nums[it] = num;
            ssum += num;
        }
#pragma unroll
        for (int o = 16; o; o >>= 1) ssum += __shfl_xor_sync(0xffffffffu, ssum, o);
        float inv = 1.f / (ssum + 1e-8f);
        float ep = 0.f;
#pragma unroll
        for (int it = 0; it < 4; it++) {
            int c = lane + it * 32;
            if (c < NC) {
                float dv = nums[it] * inv;
                ep += dv * logf(dv + 1e-20f);
                outXs[(size_t)gr * (NC * NITER) + (size_t)c * NITER + t] = dv;
                Xout[(size_t)gr * NCP + c] = Xin[(size_t)gr * NCP + c] + dv;
            } else {
                Xout[(size_t)gr * NCP + c] = 0.f;
            }
        }
#pragma unroll
        for (int o = 16; o; o >>= 1) ep += __shfl_xor_sync(0xffffffffu, ep, o);
        if (lane == 0) outEnt[(size_t)gr * NITER + t] = -ep;
    }
}

extern "C" void kernel_launch(void* const* d_in, const int* in_sizes, int n_in,
                              void* d_out, int out_size) {
    (void)in_sizes; (void)n_in; (void)out_size;
    const float* emb = (const float*)d_in[0];
    const int* labels = (const int*)d_in[1];
    float* out = (float*)d_out;
    float* outXs = out;                                   // [B, NC, NITER]
    float* outEnt = out + (size_t)BSZ * NC * NITER;       // [B, NITER]

    k_normalize<<<BSZ, 256>>>(emb);
    k_gemmA<<<dim3(BSZ / TN2, BSZ / TM2), 256>>>();
    k_mean1<<<1024, 256>>>();
    k_mean2<<<1, 1024>>>();
    k_threshold<<<4096, 256>>>();
    k_initX<<<BSZ, NCP>>>(labels);
    for (int t = 0; t < NITER; t++)
        k_iter<<<BSZ / TMI, 256>>>(t, outXs, outEnt);
}

// round 4
// speedup vs baseline: 6.3333x; 6.3333x over previous
#include <cuda_runtime.h>
#include <cuda_bf16.h>
#include <cstdint>

#define BSZ   4096
#define DIM   1024
#define NC    100
#define NCP   128
#define NITER 30
#define NLAB  2048

// ---- scratch (static device globals; no runtime allocation) ----
__device__ float g_ne[(size_t)BSZ * DIM];                  // normalized embeddings (16 MB)
__device__ float g_A[(size_t)BSZ * BSZ];                   // affinity fp32 (64 MB)
__device__ __nv_bfloat16 g_Ah[(size_t)BSZ * BSZ];          // A hi split (32 MB)
__device__ __nv_bfloat16 g_Al[(size_t)BSZ * BSZ];          // A lo split (32 MB)
__device__ float g_Xf[2][(size_t)BSZ * NCP];               // X fp32 ping-pong
__device__ __nv_bfloat16 g_Xth[2][(size_t)NCP * BSZ];      // X^T hi [N=128][K=4096]
__device__ __nv_bfloat16 g_Xtl[2][(size_t)NCP * BSZ];      // X^T lo
__device__ float g_part[1024];
__device__ float g_mean;

// ==================== small asm helpers (all base-PTX, sm_80-era) ====================
__device__ __forceinline__ uint32_t smem_u32(const void* p) {
    uint32_t a;
    asm("{ .reg .u64 t; cvta.to.shared.u64 t, %1; cvt.u32.u64 %0, t; }" : "=r"(a) : "l"(p));
    return a;
}
__device__ __forceinline__ void cp16(uint32_t dst, const void* src) {
    asm volatile("cp.async.cg.shared.global [%0], [%1], 16;"
                 :: "r"(dst), "l"(__cvta_generic_to_global(src)) : "memory");
}
__device__ __forceinline__ void cp_commit() {
    asm volatile("cp.async.commit_group;" ::: "memory");
}
template <int N>
__device__ __forceinline__ void cp_wait() {
    asm volatile("cp.async.wait_group %0;" :: "n"(N) : "memory");
}
__device__ __forceinline__ void ldmx4(uint32_t* r, uint32_t addr) {
    asm volatile("ldmatrix.sync.aligned.m8n8.x4.shared.b16 {%0,%1,%2,%3}, [%4];"
                 : "=r"(r[0]), "=r"(r[1]), "=r"(r[2]), "=r"(r[3]) : "r"(addr));
}
__device__ __forceinline__ void mma16816(float* d, const uint32_t* a, const uint32_t* b) {
    asm volatile("mma.sync.aligned.m16n8k16.row.col.f32.bf16.bf16.f32 "
                 "{%0,%1,%2,%3}, {%4,%5,%6,%7}, {%8,%9}, {%0,%1,%2,%3};"
                 : "+f"(d[0]), "+f"(d[1]), "+f"(d[2]), "+f"(d[3])
                 : "r"(a[0]), "r"(a[1]), "r"(a[2]), "r"(a[3]), "r"(b[0]), "r"(b[1]));
}
// row-stride-128B tile swizzle (conflict-free for cp.async stores + ldmatrix reads)
__device__ __forceinline__ uint32_t swz(uint32_t row, uint32_t gran16) {
    return (row * 128u + gran16 * 16u) ^ ((row & 7u) << 4);
}

// ---- f32x2 helpers (packed fp32 FMA) for SIMT gemmA ----
__device__ __forceinline__ unsigned long long bcast2(float x) {
    unsigned long long r;
    asm("mov.b64 %0, {%1, %1};" : "=l"(r) : "f"(x));
    return r;
}
__device__ __forceinline__ void ffma2(unsigned long long& d, unsigned long long a, unsigned long long b) {
    asm("fma.rn.f32x2 %0, %1, %2, %0;" : "+l"(d) : "l"(a), "l"(b));
}
__device__ __forceinline__ float lo2(unsigned long long v) { return __uint_as_float((unsigned)v); }
__device__ __forceinline__ float hi2(unsigned long long v) { return __uint_as_float((unsigned)(v >> 32)); }

// ==================== K1: row-normalize ====================
__global__ void k_normalize(const float* __restrict__ emb) {
    int r = blockIdx.x;
    int tid = threadIdx.x;
    float4 x = ((const float4*)(emb + (size_t)r * DIM))[tid];
    float ss = x.x * x.x + x.y * x.y + x.z * x.z + x.w * x.w;
    __shared__ float red[8];
#pragma unroll
    for (int o = 16; o; o >>= 1) ss += __shfl_xor_sync(0xffffffffu, ss, o);
    if ((tid & 31) == 0) red[tid >> 5] = ss;
    __syncthreads();
    float tot = red[0] + red[1] + red[2] + red[3] + red[4] + red[5] + red[6] + red[7];
    float sc = 1.f / (sqrtf(tot) + 1e-12f);
    x.x *= sc; x.y *= sc; x.z *= sc; x.w *= sc;
    ((float4*)(g_ne + (size_t)r * DIM))[tid] = x;
}

// ==================== K2: A = clamp(ne @ ne^T) (SIMT fp32, symmetric) ====================
#define TM2 128
#define TN2 64
#define TK2 16
#define ATLD 132
#define BSLD 68
#define CSLD 69

__global__ void __launch_bounds__(256) k_gemmA() {
    __shared__ __align__(16) float sm[TM2 * CSLD];
    float* At = sm;
    float* Bs = sm + TK2 * ATLD;
    int r0 = blockIdx.y * TM2;
    int c0 = blockIdx.x * TN2;
    if (c0 + TN2 <= r0) return;
    int tid = threadIdx.x;
    int tx = tid & 15, ty = tid >> 4;
    int m0 = ty * 8, n0 = tx * 4;
    unsigned long long acc[4][4];
#pragma unroll
    for (int p = 0; p < 4; p++)
#pragma unroll
        for (int n = 0; n < 4; n++) acc[p][n] = 0ULL;

    for (int k0 = 0; k0 < DIM; k0 += TK2) {
        __syncthreads();
#pragma unroll
        for (int i = 0; i < 2; i++) {
            int s = tid + i * 256;
            int r = s >> 2, q = (s & 3) * 4;
            float4 v = *(const float4*)(g_ne + (size_t)(r0 + r) * DIM + k0 + q);
            At[(q + 0) * ATLD + r] = v.x;
            At[(q + 1) * ATLD + r] = v.y;
            At[(q + 2) * ATLD + r] = v.z;
            At[(q + 3) * ATLD + r] = v.w;
        }
        {
            int r = tid >> 2, q = (tid & 3) * 4;
            float4 v = *(const float4*)(g_ne + (size_t)(c0 + r) * DIM + k0 + q);
            Bs[(q + 0) * BSLD + r] = v.x;
            Bs[(q + 1) * BSLD + r] = v.y;
            Bs[(q + 2) * BSLD + r] = v.z;
            Bs[(q + 3) * BSLD + r] = v.w;
        }
        __syncthreads();
#pragma unroll
        for (int k = 0; k < TK2; k++) {
            ulonglong2 aA = *(const ulonglong2*)(At + k * ATLD + m0);
            ulonglong2 aB = *(const ulonglong2*)(At + k * ATLD + m0 + 4);
            float4 bv = *(const float4*)(Bs + k * BSLD + n0);
            unsigned long long b0 = bcast2(bv.x), b1 = bcast2(bv.y);
            unsigned long long b2 = bcast2(bv.z), b3 = bcast2(bv.w);
            ffma2(acc[0][0], aA.x, b0); ffma2(acc[0][1], aA.x, b1);
            ffma2(acc[0][2], aA.x, b2); ffma2(acc[0][3], aA.x, b3);
            ffma2(acc[1][0], aA.y, b0); ffma2(acc[1][1], aA.y, b1);
            ffma2(acc[1][2], aA.y, b2); ffma2(acc[1][3], aA.y, b3);
            ffma2(acc[2][0], aB.x, b0); ffma2(acc[2][1], aB.x, b1);
            ffma2(acc[2][2], aB.x, b2); ffma2(acc[2][3], aB.x, b3);
            ffma2(acc[3][0], aB.y, b0); ffma2(acc[3][1], aB.y, b1);
            ffma2(acc[3][2], aB.y, b2); ffma2(acc[3][3], aB.y, b3);
        }
    }
    __syncthreads();
#pragma unroll
    for (int p = 0; p < 4; p++)
#pragma unroll
        for (int n = 0; n < 4; n++) {
            sm[(m0 + 2 * p) * CSLD + n0 + n]     = lo2(acc[p][n]);
            sm[(m0 + 2 * p + 1) * CSLD + n0 + n] = hi2(acc[p][n]);
        }
    __syncthreads();
    for (int idx = tid; idx < TM2 * TN2; idx += 256) {
        int i = idx >> 6, j = idx & 63;
        int gi = r0 + i, gj = c0 + j;
        float v = sm[i * CSLD + j];
        v = (gi == gj) ? 0.f : fminf(fmaxf(v, 0.f), 1.f);
        g_A[(size_t)gi * BSZ + gj] = v;
    }
    for (int idx = tid; idx < TM2 * TN2; idx += 256) {
        int jj = idx >> 7, ii = idx & 127;
        int gi = r0 + ii, gj = c0 + jj;
        float v = sm[ii * CSLD + jj];
        v = (gi == gj) ? 0.f : fminf(fmaxf(v, 0.f), 1.f);
        g_A[(size_t)gj * BSZ + gi] = v;
    }
}

// ==================== K3/K4: deterministic mean ====================
__global__ void k_mean1() {
    int tid = threadIdx.x;
    size_t base = (size_t)blockIdx.x * 4096 + tid;
    const float4* A4 = (const float4*)g_A;
    float s = 0.f;
#pragma unroll
    for (int i = 0; i < 16; i++) {
        float4 v = A4[base + (size_t)i * 256];
        s += (v.x + v.y) + (v.z + v.w);
    }
    __shared__ float red[8];
#pragma unroll
    for (int o = 16; o; o >>= 1) s += __shfl_xor_sync(0xffffffffu, s, o);
    if ((tid & 31) == 0) red[tid >> 5] = s;
    __syncthreads();
    if (tid == 0) {
        float t = 0.f;
#pragma unroll
        for (int i = 0; i < 8; i++) t += red[i];
        g_part[blockIdx.x] = t;
    }
}

__global__ void k_mean2() {
    __shared__ float red[1024];
    int tid = threadIdx.x;
    red[tid] = g_part[tid];
    __syncthreads();
    for (int o = 512; o; o >>= 1) {
        if (tid < o) red[tid] += red[tid + o];
        __syncthreads();
    }
    if (tid == 0) g_mean = red[0] * (1.f / ((float)BSZ * (float)BSZ));
}

// ==================== K5: threshold + bf16 hi/lo split of A ====================
__global__ void k_splitA() {
    float m = g_mean;
    size_t i = ((size_t)blockIdx.x * 256 + threadIdx.x) * 8;
    float4 v0 = *(const float4*)(g_A + i);
    float4 v1 = *(const float4*)(g_A + i + 4);
    float f[8] = {v0.x, v0.y, v0.z, v0.w, v1.x, v1.y, v1.z, v1.w};
    uint32_t hw[4], lw[4];
#pragma unroll
    for (int j = 0; j < 4; j++) {
        float f0 = (f[2 * j]     < m) ? 0.f : f[2 * j];
        float f1 = (f[2 * j + 1] < m) ? 0.f : f[2 * j + 1];
        __nv_bfloat16 h0 = __float2bfloat16(f0), h1 = __float2bfloat16(f1);
        __nv_bfloat16 l0 = __float2bfloat16(f0 - __bfloat162float(h0));
        __nv_bfloat16 l1 = __float2bfloat16(f1 - __bfloat162float(h1));
        hw[j] = (uint32_t)__bfloat16_as_ushort(h0) | ((uint32_t)__bfloat16_as_ushort(h1) << 16);
        lw[j] = (uint32_t)__bfloat16_as_ushort(l0) | ((uint32_t)__bfloat16_as_ushort(l1) << 16);
    }
    *(uint4*)(g_Ah + i) = make_uint4(hw[0], hw[1], hw[2], hw[3]);
    *(uint4*)(g_Al + i) = make_uint4(lw[0], lw[1], lw[2], lw[3]);
}

// ==================== K6: init X (fp32 + transposed bf16 split) ====================
__global__ void k_initX(const int* __restrict__ labels) {
    int r = blockIdx.x, c = threadIdx.x;
    float v;
    if (r < NLAB) v = (c == labels[r]) ? 1.f : 0.f;
    else          v = (c < NC) ? 0.01f : 0.f;
    g_Xf[0][(size_t)r * NCP + c] = v;
    __nv_bfloat16 h = __float2bfloat16(v);
    g_Xth[0][(size_t)c * BSZ + r] = h;
    g_Xtl[0][(size_t)c * BSZ + r] = __float2bfloat16(v - __bfloat162float(h));
}

// ==================== K7: HMMA replicator iteration ====================
// CTA: M-tile 32, N=128, 128 threads (4 warps), warp tile 32m x 32n.
// K-chunks of 64, 2-stage cp.async pipeline.
// D = Ah@Xh + Ah@Xl + Al@Xh (bf16 split-3, fp32 accum).
#define KC 64
#define NCHUNK (BSZ / KC)
#define AH_OFF 0
#define AL_OFF 4096
#define XH_OFF 8192
#define XL_OFF 24576
#define STAGE_B 40960
#define DSMEM (1024 + 2 * STAGE_B)

__global__ void __launch_bounds__(128, 1) k_iter_mma(int t, float* __restrict__ outXs,
                                                     float* __restrict__ outEnt) {
    extern __shared__ char dsm[];
    __shared__ uint32_t sp[NCP * 32];     // staged packed hi|lo bf16 of next X (16 KB)
    __shared__ float srow[32][4];
    __shared__ float sent[32][4];

    uint32_t raw = smem_u32(dsm);
    uint32_t sbase = (raw + 1023u) & ~1023u;

    int tid = threadIdx.x;
    int wid = tid >> 5, lane = tid & 31;
    int r0 = blockIdx.x * 32;

    const __nv_bfloat16* __restrict__ Ah = g_Ah;
    const __nv_bfloat16* __restrict__ Al = g_Al;
    const __nv_bfloat16* __restrict__ Xth = g_Xth[t & 1];
    const __nv_bfloat16* __restrict__ Xtl = g_Xtl[t & 1];

    // ---- stage loader: 20 cp.async x 16B per thread ----
    auto load_stage = [&](int c, int buf) {
        uint32_t bu = sbase + buf * STAGE_B;
        int k0 = c * KC;
        int g = tid & 7;
        int rbase = tid >> 3;                     // 0..15
#pragma unroll
        for (int j = 0; j < 2; j++) {
            int row = rbase + 16 * j;             // 0..31
            size_t ga = (size_t)(r0 + row) * BSZ + k0 + g * 8;
            cp16(bu + AH_OFF + swz(row, g), Ah + ga);
            cp16(bu + AL_OFF + swz(row, g), Al + ga);
        }
#pragma unroll
        for (int j = 0; j < 8; j++) {
            int row = rbase + 16 * j;             // 0..127
            size_t gx = (size_t)row * BSZ + k0 + g * 8;
            cp16(bu + XH_OFF + swz(row, g), Xth + gx);
            cp16(bu + XL_OFF + swz(row, g), Xtl + gx);
        }
        cp_commit();
    };

    float acc[2][4][4];
#pragma unroll
    for (int q = 0; q < 2; q++)
#pragma unroll
        for (int nt = 0; nt < 4; nt++)
#pragma unroll
            for (int e = 0; e < 4; e++) acc[q][nt][e] = 0.f;

    load_stage(0, 0);
    load_stage(1, 1);

    for (int c = 0; c < NCHUNK; c++) {
        if (c == NCHUNK - 1) cp_wait<0>(); else cp_wait<1>();
        __syncthreads();
        uint32_t bu = sbase + (c & 1) * STAGE_B;
#pragma unroll
        for (int ks = 0; ks < 4; ks++) {
            uint32_t ah[2][4], al2[2][4];
#pragma unroll
            for (int q = 0; q < 2; q++) {
                uint32_t off = swz(q * 16 + (lane & 15), ks * 2 + (lane >> 4));
                ldmx4(ah[q],  bu + AH_OFF + off);
                ldmx4(al2[q], bu + AL_OFF + off);
            }
            uint32_t bh[4][2], bl[4][2];
#pragma unroll
            for (int p = 0; p < 2; p++) {
                uint32_t row = wid * 32 + p * 16 + (lane & 7) + ((lane >> 4) & 1) * 8;
                uint32_t off = swz(row, ks * 2 + ((lane >> 3) & 1));
                uint32_t t4[4];
                ldmx4(t4, bu + XH_OFF + off);
                bh[2 * p][0] = t4[0]; bh[2 * p][1] = t4[1];
                bh[2 * p + 1][0] = t4[2]; bh[2 * p + 1][1] = t4[3];
                ldmx4(t4, bu + XL_OFF + off);
                bl[2 * p][0] = t4[0]; bl[2 * p][1] = t4[1];
                bl[2 * p + 1][0] = t4[2]; bl[2 * p + 1][1] = t4[3];
            }
#pragma unroll
            for (int q = 0; q < 2; q++)
#pragma unroll
                for (int nt = 0; nt < 4; nt++) {
                    mma16816(acc[q][nt], ah[q], bh[nt]);
                    mma16816(acc[q][nt], ah[q], bl[nt]);
                    mma16816(acc[q][nt], al2[q], bh[nt]);
                }
        }
        __syncthreads();
        if (c + 2 < NCHUNK) load_stage(c + 2, c & 1);
    }

    // ---- fused epilogue ----
    const float* __restrict__ Xin  = g_Xf[t & 1];
    float* __restrict__ Xout = g_Xf[(t + 1) & 1];

    // thread owns 4 rows: rr = q*2 + hi -> row = q*16 + hi*8 + (lane>>2)
    // cols: cb(nt) = wid*32 + nt*8 + 2*(lane&3); D elems: acc[q][nt][hi*2 + e]
    float xv[4][4][2];
    int cb = wid * 32 + 2 * (lane & 3);

#pragma unroll
    for (int rr = 0; rr < 4; rr++) {
        int row = (rr >> 1) * 16 + (rr & 1) * 8 + (lane >> 2);
        int gr = r0 + row;
        float s = 0.f;
#pragma unroll
        for (int nt = 0; nt < 4; nt++) {
            float2 x2 = *(const float2*)(Xin + (size_t)gr * NCP + cb + nt * 8);
            xv[rr][nt][0] = x2.x; xv[rr][nt][1] = x2.y;
            int q = rr >> 1, hb = (rr & 1) * 2;
#pragma unroll
            for (int e = 0; e < 2; e++) {
                int cc = cb + nt * 8 + e;
                if (cc < NC) s += xv[rr][nt][e] * acc[q][nt][hb + e];
            }
        }
        s += __shfl_xor_sync(0xffffffffu, s, 1);
        s += __shfl_xor_sync(0xffffffffu, s, 2);
        if ((lane & 3) == 0) srow[row][wid] = s;
    }
    __syncthreads();

#pragma unroll
    for (int rr = 0; rr < 4; rr++) {
        int row = (rr >> 1) * 16 + (rr & 1) * 8 + (lane >> 2);
        int gr = r0 + row;
        float tot = srow[row][0] + srow[row][1] + srow[row][2] + srow[row][3];
        float inv = 1.f / (tot + 1e-8f);
        float ep = 0.f;
        int q = rr >> 1, hb = (rr & 1) * 2;
#pragma unroll
        for (int nt = 0; nt < 4; nt++) {
            float xo2[2];
#pragma unroll
            for (int e = 0; e < 2; e++) {
                int cc = cb + nt * 8 + e;
                float xvv = xv[rr][nt][e];
                float num = (cc < NC) ? xvv * acc[q][nt][hb + e] : 0.f;
                float dv = num * inv;
                float xo = xvv + dv;
                if (cc < NC) {
                    ep += dv * __logf(dv + 1e-20f);
                    outXs[(size_t)gr * (NC * NITER) + (size_t)cc * NITER + t] = dv;
                }
                xo2[e] = xo;
                __nv_bfloat16 h = __float2bfloat16(xo);
                __nv_bfloat16 l = __float2bfloat16(xo - __bfloat162float(h));
                sp[cc * 32 + row] = (uint32_t)__bfloat16_as_ushort(h) |
                                    ((uint32_t)__bfloat16_as_ushort(l) << 16);
            }
            *(float2*)(Xout + (size_t)gr * NCP + cb + nt * 8) = make_float2(xo2[0], xo2[1]);
        }
        ep += __shfl_xor_sync(0xffffffffu, ep, 1);
        ep += __shfl_xor_sync(0xffffffffu, ep, 2);
        if ((lane & 3) == 0) sent[row][wid] = ep;
    }
    __syncthreads();

    if (tid < 32) {
        float e4 = sent[tid][0] + sent[tid][1] + sent[tid][2] + sent[tid][3];
        outEnt[(size_t)(r0 + tid) * NITER + t] = -e4;
    }

    // coalesced transposed write-out of next X^T hi/lo
    __nv_bfloat16* XthN = g_Xth[(t + 1) & 1];
    __nv_bfloat16* XtlN = g_Xtl[(t + 1) & 1];
    for (int idx = tid; idx < NCP * 16; idx += 128) {
        int cc = idx >> 4;
        int pos = (idx & 15) * 2;
        uint32_t p0 = sp[cc * 32 + pos];
        uint32_t p1 = sp[cc * 32 + pos + 1];
        uint32_t hi = (p0 & 0xFFFFu) | (p1 << 16);
        uint32_t lo = (p0 >> 16) | (p1 & 0xFFFF0000u);
        *(uint32_t*)(XthN + (size_t)cc * BSZ + r0 + pos) = hi;
        *(uint32_t*)(XtlN + (size_t)cc * BSZ + r0 + pos) = lo;
    }
}

// ==================== launch ====================
extern "C" void kernel_launch(void* const* d_in, const int* in_sizes, int n_in,
                              void* d_out, int out_size) {
    (void)in_sizes; (void)n_in; (void)out_size;
    const float* emb = (const float*)d_in[0];
    const int* labels = (const int*)d_in[1];
    float* out = (float*)d_out;
    float* outXs = out;                                 // [B, NC, NITER]
    float* outEnt = out + (size_t)BSZ * NC * NITER;     // [B, NITER]

    cudaFuncSetAttribute(k_iter_mma, cudaFuncAttributeMaxDynamicSharedMemorySize, DSMEM);

    k_normalize<<<BSZ, 256>>>(emb);
    k_gemmA<<<dim3(BSZ / TN2, BSZ / TM2), 256>>>();
    k_mean1<<<1024, 256>>>();
    k_mean2<<<1, 1024>>>();
    k_splitA<<<(int)(((size_t)BSZ * BSZ) / (8 * 256)), 256>>>();
    k_initX<<<BSZ, NCP>>>(labels);
    for (int t = 0; t < NITER; t++)
        k_iter_mma<<<BSZ / 32, 128, DSMEM>>>(t, outXs, outEnt);
}

// round 5
// speedup vs baseline: 7.1800x; 1.1337x over previous
#include <cuda_runtime.h>
#include <cuda_bf16.h>
#include <cstdint>

#define BSZ   4096
#define DIM   1024
#define NC    100
#define NCP   128
#define NITER 30
#define NLAB  2048

// ---- scratch (static device globals; no runtime allocation) ----
__device__ __nv_bfloat16 g_neh[(size_t)BSZ * DIM];         // normalized emb hi (8 MB)
__device__ __nv_bfloat16 g_nel[(size_t)BSZ * DIM];         // normalized emb lo (8 MB)
__device__ float g_A[(size_t)BSZ * BSZ];                   // affinity fp32 (64 MB)
__device__ __nv_bfloat16 g_Ah[(size_t)BSZ * BSZ];          // A hi split (32 MB)
__device__ __nv_bfloat16 g_Al[(size_t)BSZ * BSZ];          // A lo split (32 MB)
__device__ float g_Xf[2][(size_t)BSZ * NCP];               // X fp32 ping-pong
__device__ __nv_bfloat16 g_Xth[2][(size_t)NCP * BSZ];      // X^T hi [N=128][K=4096]
__device__ __nv_bfloat16 g_Xtl[2][(size_t)NCP * BSZ];      // X^T lo
__device__ float g_part[1024];
__device__ float g_mean;

// ==================== asm helpers (base PTX, sm_80-era) ====================
__device__ __forceinline__ uint32_t smem_u32(const void* p) {
    uint32_t a;
    asm("{ .reg .u64 t; cvta.to.shared.u64 t, %1; cvt.u32.u64 %0, t; }" : "=r"(a) : "l"(p));
    return a;
}
__device__ __forceinline__ void cp16(uint32_t dst, const void* src) {
    asm volatile("cp.async.cg.shared.global [%0], [%1], 16;"
                 :: "r"(dst), "l"(__cvta_generic_to_global(src)) : "memory");
}
__device__ __forceinline__ void cp_commit() {
    asm volatile("cp.async.commit_group;" ::: "memory");
}
template <int N>
__device__ __forceinline__ void cp_wait() {
    asm volatile("cp.async.wait_group %0;" :: "n"(N) : "memory");
}
__device__ __forceinline__ void ldmx4(uint32_t* r, uint32_t addr) {
    asm volatile("ldmatrix.sync.aligned.m8n8.x4.shared.b16 {%0,%1,%2,%3}, [%4];"
                 : "=r"(r[0]), "=r"(r[1]), "=r"(r[2]), "=r"(r[3]) : "r"(addr));
}
__device__ __forceinline__ void mma16816(float* d, const uint32_t* a, const uint32_t* b) {
    asm volatile("mma.sync.aligned.m16n8k16.row.col.f32.bf16.bf16.f32 "
                 "{%0,%1,%2,%3}, {%4,%5,%6,%7}, {%8,%9}, {%0,%1,%2,%3};"
                 : "+f"(d[0]), "+f"(d[1]), "+f"(d[2]), "+f"(d[3])
                 : "r"(a[0]), "r"(a[1]), "r"(a[2]), "r"(a[3]), "r"(b[0]), "r"(b[1]));
}
// row-stride-128B tile swizzle (conflict-free for cp.async stores + ldmatrix reads)
__device__ __forceinline__ uint32_t swz(uint32_t row, uint32_t gran16) {
    return (row * 128u + gran16 * 16u) ^ ((row & 7u) << 4);
}
__device__ __forceinline__ uint32_t pack_hl(float v, float* lo_f = nullptr) {
    __nv_bfloat16 h = __float2bfloat16(v);
    __nv_bfloat16 l = __float2bfloat16(v - __bfloat162float(h));
    (void)lo_f;
    return (uint32_t)__bfloat16_as_ushort(h) | ((uint32_t)__bfloat16_as_ushort(l) << 16);
}

// ==================== K1: row-normalize -> bf16 hi/lo ====================
__global__ void k_normalize(const float* __restrict__ emb) {
    int r = blockIdx.x;
    int tid = threadIdx.x;                       // 256 threads, 4 floats each
    float4 x = ((const float4*)(emb + (size_t)r * DIM))[tid];
    float ss = x.x * x.x + x.y * x.y + x.z * x.z + x.w * x.w;
    __shared__ float red[8];
#pragma unroll
    for (int o = 16; o; o >>= 1) ss += __shfl_xor_sync(0xffffffffu, ss, o);
    if ((tid & 31) == 0) red[tid >> 5] = ss;
    __syncthreads();
    float tot = red[0] + red[1] + red[2] + red[3] + red[4] + red[5] + red[6] + red[7];
    float sc = 1.f / (sqrtf(tot) + 1e-12f);
    float v[4] = {x.x * sc, x.y * sc, x.z * sc, x.w * sc};
    uint32_t hh[2], ll[2];
#pragma unroll
    for (int j = 0; j < 2; j++) {
        __nv_bfloat16 h0 = __float2bfloat16(v[2 * j]);
        __nv_bfloat16 h1 = __float2bfloat16(v[2 * j + 1]);
        __nv_bfloat16 l0 = __float2bfloat16(v[2 * j] - __bfloat162float(h0));
        __nv_bfloat16 l1 = __float2bfloat16(v[2 * j + 1] - __bfloat162float(h1));
        hh[j] = (uint32_t)__bfloat16_as_ushort(h0) | ((uint32_t)__bfloat16_as_ushort(h1) << 16);
        ll[j] = (uint32_t)__bfloat16_as_ushort(l0) | ((uint32_t)__bfloat16_as_ushort(l1) << 16);
    }
    ((uint2*)(g_neh + (size_t)r * DIM))[tid] = make_uint2(hh[0], hh[1]);
    ((uint2*)(g_nel + (size_t)r * DIM))[tid] = make_uint2(ll[0], ll[1]);
}

// ==================== K2: A = clamp(ne @ ne^T) via HMMA split-3, symmetric ====================
#define GT 32                          // 4096/128 tiles per dim
#define AKC 64
#define ACH (DIM / AKC)                // 16 chunks
#define A_AH 0
#define A_AL 16384
#define A_BH 32768
#define A_BL 49152
#define A_STAGE 65536
#define A_DSMEM (1024 + 2 * A_STAGE)   // 132 KB

__global__ void __launch_bounds__(256, 1) k_gemmA_mma() {
    extern __shared__ char dsm[];
    uint32_t raw = smem_u32(dsm);
    uint32_t sbase = ((raw + 1023u) & ~1023u);
    char* sgen = dsm + (sbase - raw);
    uint32_t stg = sbase;

    int tid = threadIdx.x, wid = tid >> 5, lane = tid & 31;
    int wm = wid >> 2, wn = wid & 3;

    // decode upper-triangle tile index: b -> (ti, tj), ti <= tj
    int b = blockIdx.x;
    int ti = 0;
    while ((ti + 1) * GT - ti * (ti + 1) / 2 <= b) ti++;
    int tj = ti + (b - (ti * GT - ti * (ti - 1) / 2));
    int r0 = ti * 128, c0 = tj * 128;

    auto load_stage = [&](int k0, int buf) {
        uint32_t bu = stg + buf * A_STAGE;
        int g = tid & 7, rb = tid >> 3;          // rb 0..31
#pragma unroll
        for (int j = 0; j < 4; j++) {
            int row = rb + 32 * j;
            size_t ga = (size_t)(r0 + row) * DIM + k0 + g * 8;
            size_t gb = (size_t)(c0 + row) * DIM + k0 + g * 8;
            uint32_t so = swz(row, g);
            cp16(bu + A_AH + so, g_neh + ga);
            cp16(bu + A_AL + so, g_nel + ga);
            cp16(bu + A_BH + so, g_neh + gb);
            cp16(bu + A_BL + so, g_nel + gb);
        }
        cp_commit();
    };

    float acc[4][4][4];
#pragma unroll
    for (int q = 0; q < 4; q++)
#pragma unroll
        for (int nt = 0; nt < 4; nt++)
#pragma unroll
            for (int e = 0; e < 4; e++) acc[q][nt][e] = 0.f;

    load_stage(0, 0);
    load_stage(AKC, 1);

    for (int c = 0; c < ACH; c++) {
        if (c == ACH - 1) cp_wait<0>(); else cp_wait<1>();
        __syncthreads();
        uint32_t bu = stg + (c & 1) * A_STAGE;
#pragma unroll
        for (int ks = 0; ks < 4; ks++) {
            uint32_t ah[4][4], al[4][4];
#pragma unroll
            for (int q = 0; q < 4; q++) {
                uint32_t off = swz(wm * 64 + q * 16 + (lane & 15), ks * 2 + (lane >> 4));
                ldmx4(ah[q], bu + A_AH + off);
                ldmx4(al[q], bu + A_AL + off);
            }
            uint32_t bh[4][2], bl[4][2];
#pragma unroll
            for (int p = 0; p < 2; p++) {
                uint32_t row = wn * 32 + p * 16 + (lane & 7) + ((lane >> 4) & 1) * 8;
                uint32_t off = swz(row, ks * 2 + ((lane >> 3) & 1));
                uint32_t t4[4];
                ldmx4(t4, bu + A_BH + off);
                bh[2 * p][0] = t4[0]; bh[2 * p][1] = t4[1];
                bh[2 * p + 1][0] = t4[2]; bh[2 * p + 1][1] = t4[3];
                ldmx4(t4, bu + A_BL + off);
                bl[2 * p][0] = t4[0]; bl[2 * p][1] = t4[1];
                bl[2 * p + 1][0] = t4[2]; bl[2 * p + 1][1] = t4[3];
            }
#pragma unroll
            for (int q = 0; q < 4; q++)
#pragma unroll
                for (int nt = 0; nt < 4; nt++) {
                    mma16816(acc[q][nt], ah[q], bh[nt]);
                    mma16816(acc[q][nt], ah[q], bl[nt]);
                    mma16816(acc[q][nt], al[q], bh[nt]);
                }
        }
        __syncthreads();
        if (c + 2 < ACH) load_stage((c + 2) * AKC, c & 1);
    }

    // ---- epilogue: stage C in smem, clamp/diag, direct + mirror writes ----
    float* Cs = (float*)sgen;                    // 128 x 130 fp32 = 66.6 KB (reuses stages)
#pragma unroll
    for (int q = 0; q < 4; q++) {
        int row = wm * 64 + q * 16 + (lane >> 2);
        int col = wn * 32 + (lane & 3) * 2;
#pragma unroll
        for (int nt = 0; nt < 4; nt++) {
            Cs[row * 130 + col + nt * 8]           = acc[q][nt][0];
            Cs[row * 130 + col + nt * 8 + 1]       = acc[q][nt][1];
            Cs[(row + 8) * 130 + col + nt * 8]     = acc[q][nt][2];
            Cs[(row + 8) * 130 + col + nt * 8 + 1] = acc[q][nt][3];
        }
    }
    __syncthreads();
    for (int idx = tid; idx < 128 * 128; idx += 256) {
        int i = idx >> 7, j = idx & 127;
        int gi = r0 + i, gj = c0 + j;
        float v = Cs[i * 130 + j];
        v = (gi == gj) ? 0.f : fminf(fmaxf(v, 0.f), 1.f);
        g_A[(size_t)gi * BSZ + gj] = v;
    }
    if (ti != tj) {
        for (int idx = tid; idx < 128 * 128; idx += 256) {
            int i = idx >> 7, j = idx & 127;     // write row c0+i, col r0+j
            float v = Cs[j * 130 + i];
            v = fminf(fmaxf(v, 0.f), 1.f);
            g_A[(size_t)(c0 + i) * BSZ + (r0 + j)] = v;
        }
    }
}

// ==================== K3/K4: deterministic mean ====================
__global__ void k_mean1() {
    int tid = threadIdx.x;
    size_t base = (size_t)blockIdx.x * 4096 + tid;
    const float4* A4 = (const float4*)g_A;
    float s = 0.f;
#pragma unroll
    for (int i = 0; i < 16; i++) {
        float4 v = A4[base + (size_t)i * 256];
        s += (v.x + v.y) + (v.z + v.w);
    }
    __shared__ float red[8];
#pragma unroll
    for (int o = 16; o; o >>= 1) s += __shfl_xor_sync(0xffffffffu, s, o);
    if ((tid & 31) == 0) red[tid >> 5] = s;
    __syncthreads();
    if (tid == 0) {
        float t = 0.f;
#pragma unroll
        for (int i = 0; i < 8; i++) t += red[i];
        g_part[blockIdx.x] = t;
    }
}

__global__ void k_mean2() {
    __shared__ float red[1024];
    int tid = threadIdx.x;
    red[tid] = g_part[tid];
    __syncthreads();
    for (int o = 512; o; o >>= 1) {
        if (tid < o) red[tid] += red[tid + o];
        __syncthreads();
    }
    if (tid == 0) g_mean = red[0] * (1.f / ((float)BSZ * (float)BSZ));
}

// ==================== K5: threshold + bf16 hi/lo split of A ====================
__global__ void k_splitA() {
    float m = g_mean;
    size_t i = ((size_t)blockIdx.x * 256 + threadIdx.x) * 8;
    float4 v0 = *(const float4*)(g_A + i);
    float4 v1 = *(const float4*)(g_A + i + 4);
    float f[8] = {v0.x, v0.y, v0.z, v0.w, v1.x, v1.y, v1.z, v1.w};
    uint32_t hw[4], lw[4];
#pragma unroll
    for (int j = 0; j < 4; j++) {
        float f0 = (f[2 * j]     < m) ? 0.f : f[2 * j];
        float f1 = (f[2 * j + 1] < m) ? 0.f : f[2 * j + 1];
        __nv_bfloat16 h0 = __float2bfloat16(f0), h1 = __float2bfloat16(f1);
        __nv_bfloat16 l0 = __float2bfloat16(f0 - __bfloat162float(h0));
        __nv_bfloat16 l1 = __float2bfloat16(f1 - __bfloat162float(h1));
        hw[j] = (uint32_t)__bfloat16_as_ushort(h0) | ((uint32_t)__bfloat16_as_ushort(h1) << 16);
        lw[j] = (uint32_t)__bfloat16_as_ushort(l0) | ((uint32_t)__bfloat16_as_ushort(l1) << 16);
    }
    *(uint4*)(g_Ah + i) = make_uint4(hw[0], hw[1], hw[2], hw[3]);
    *(uint4*)(g_Al + i) = make_uint4(lw[0], lw[1], lw[2], lw[3]);
}

// ==================== K6: init X (fp32 + transposed bf16 split) ====================
__global__ void k_initX(const int* __restrict__ labels) {
    int r = blockIdx.x, c = threadIdx.x;
    float v;
    if (r < NLAB) v = (c == labels[r]) ? 1.f : 0.f;
    else          v = (c < NC) ? 0.01f : 0.f;
    g_Xf[0][(size_t)r * NCP + c] = v;
    __nv_bfloat16 h = __float2bfloat16(v);
    g_Xth[0][(size_t)c * BSZ + r] = h;
    g_Xtl[0][(size_t)c * BSZ + r] = __float2bfloat16(v - __bfloat162float(h));
}

// ==================== K7: HMMA replicator iteration ====================
#define KC 64
#define NCHUNK (BSZ / KC)
#define AH_OFF 0
#define AL_OFF 4096
#define XH_OFF 8192
#define XL_OFF 24576
#define STAGE_B 40960
#define DSMEM (1024 + 2 * STAGE_B)

__global__ void __launch_bounds__(128, 1) k_iter_mma(int t, float* __restrict__ outXs,
                                                     float* __restrict__ outEnt) {
    extern __shared__ char dsm[];
    __shared__ uint32_t sp[NCP * 32];     // staged packed hi|lo bf16 of next X (16 KB)
    __shared__ float srow[32][4];
    __shared__ float sent[32][4];

    uint32_t raw = smem_u32(dsm);
    uint32_t sbase = (raw + 1023u) & ~1023u;

    int tid = threadIdx.x;
    int wid = tid >> 5, lane = tid & 31;
    int r0 = blockIdx.x * 32;

    const __nv_bfloat16* __restrict__ Ah = g_Ah;
    const __nv_bfloat16* __restrict__ Al = g_Al;
    const __nv_bfloat16* __restrict__ Xth = g_Xth[t & 1];
    const __nv_bfloat16* __restrict__ Xtl = g_Xtl[t & 1];

    auto load_stage = [&](int c, int buf) {
        uint32_t bu = sbase + buf * STAGE_B;
        int k0 = c * KC;
        int g = tid & 7;
        int rbase = tid >> 3;
#pragma unroll
        for (int j = 0; j < 2; j++) {
            int row = rbase + 16 * j;
            size_t ga = (size_t)(r0 + row) * BSZ + k0 + g * 8;
            cp16(bu + AH_OFF + swz(row, g), Ah + ga);
            cp16(bu + AL_OFF + swz(row, g), Al + ga);
        }
#pragma unroll
        for (int j = 0; j < 8; j++) {
            int row = rbase + 16 * j;
            size_t gx = (size_t)row * BSZ + k0 + g * 8;
            cp16(bu + XH_OFF + swz(row, g), Xth + gx);
            cp16(bu + XL_OFF + swz(row, g), Xtl + gx);
        }
        cp_commit();
    };

    float acc[2][4][4];
#pragma unroll
    for (int q = 0; q < 2; q++)
#pragma unroll
        for (int nt = 0; nt < 4; nt++)
#pragma unroll
            for (int e = 0; e < 4; e++) acc[q][nt][e] = 0.f;

    load_stage(0, 0);
    load_stage(1, 1);

    for (int c = 0; c < NCHUNK; c++) {
        if (c == NCHUNK - 1) cp_wait<0>(); else cp_wait<1>();
        __syncthreads();
        uint32_t bu = sbase + (c & 1) * STAGE_B;
#pragma unroll
        for (int ks = 0; ks < 4; ks++) {
            uint32_t ah[2][4], al2[2][4];
#pragma unroll
            for (int q = 0; q < 2; q++) {
                uint32_t off = swz(q * 16 + (lane & 15), ks * 2 + (lane >> 4));
                ldmx4(ah[q],  bu + AH_OFF + off);
                ldmx4(al2[q], bu + AL_OFF + off);
            }
            uint32_t bh[4][2], bl[4][2];
#pragma unroll
            for (int p = 0; p < 2; p++) {
                uint32_t row = wid * 32 + p * 16 + (lane & 7) + ((lane >> 4) & 1) * 8;
                uint32_t off = swz(row, ks * 2 + ((lane >> 3) & 1));
                uint32_t t4[4];
                ldmx4(t4, bu + XH_OFF + off);
                bh[2 * p][0] = t4[0]; bh[2 * p][1] = t4[1];
                bh[2 * p + 1][0] = t4[2]; bh[2 * p + 1][1] = t4[3];
                ldmx4(t4, bu + XL_OFF + off);
                bl[2 * p][0] = t4[0]; bl[2 * p][1] = t4[1];
                bl[2 * p + 1][0] = t4[2]; bl[2 * p + 1][1] = t4[3];
            }
#pragma unroll
            for (int q = 0; q < 2; q++)
#pragma unroll
                for (int nt = 0; nt < 4; nt++) {
                    mma16816(acc[q][nt], ah[q], bh[nt]);
                    mma16816(acc[q][nt], ah[q], bl[nt]);
                    mma16816(acc[q][nt], al2[q], bh[nt]);
                }
        }
        __syncthreads();
        if (c + 2 < NCHUNK) load_stage(c + 2, c & 1);
    }

    // ---- fused epilogue ----
    const float* __restrict__ Xin  = g_Xf[t & 1];
    float* __restrict__ Xout = g_Xf[(t + 1) & 1];

    float xv[4][4][2];
    int cb = wid * 32 + 2 * (lane & 3);

#pragma unroll
    for (int rr = 0; rr < 4; rr++) {
        int row = (rr >> 1) * 16 + (rr & 1) * 8 + (lane >> 2);
        int gr = r0 + row;
        float s = 0.f;
#pragma unroll
        for (int nt = 0; nt < 4; nt++) {
            float2 x2 = *(const float2*)(Xin + (size_t)gr * NCP + cb + nt * 8);
            xv[rr][nt][0] = x2.x; xv[rr][nt][1] = x2.y;
            int q = rr >> 1, hb = (rr & 1) * 2;
#pragma unroll
            for (int e = 0; e < 2; e++) {
                int cc = cb + nt * 8 + e;
                if (cc < NC) s += xv[rr][nt][e] * acc[q][nt][hb + e];
            }
        }
        s += __shfl_xor_sync(0xffffffffu, s, 1);
        s += __shfl_xor_sync(0xffffffffu, s, 2);
        if ((lane & 3) == 0) srow[row][wid] = s;
    }
    __syncthreads();

#pragma unroll
    for (int rr = 0; rr < 4; rr++) {
        int row = (rr >> 1) * 16 + (rr & 1) * 8 + (lane >> 2);
        int gr = r0 + row;
        float tot = srow[row][0] + srow[row][1] + srow[row][2] + srow[row][3];
        float inv = 1.f / (tot + 1e-8f);
        float ep = 0.f;
        int q = rr >> 1, hb = (rr & 1) * 2;
#pragma unroll
        for (int nt = 0; nt < 4; nt++) {
            float xo2[2];
#pragma unroll
            for (int e = 0; e < 2; e++) {
                int cc = cb + nt * 8 + e;
                float xvv = xv[rr][nt][e];
                float num = (cc < NC) ? xvv * acc[q][nt][hb + e] : 0.f;
                float dv = num * inv;
                float xo = xvv + dv;
                if (cc < NC) {
                    ep += dv * __logf(dv + 1e-20f);
                    outXs[(size_t)gr * (NC * NITER) + (size_t)cc * NITER + t] = dv;
                }
                xo2[e] = xo;
                __nv_bfloat16 h = __float2bfloat16(xo);
                __nv_bfloat16 l = __float2bfloat16(xo - __bfloat162float(h));
                sp[cc * 32 + row] = (uint32_t)__bfloat16_as_ushort(h) |
                                    ((uint32_t)__bfloat16_as_ushort(l) << 16);
            }
            *(float2*)(Xout + (size_t)gr * NCP + cb + nt * 8) = make_float2(xo2[0], xo2[1]);
        }
        ep += __shfl_xor_sync(0xffffffffu, ep, 1);
        ep += __shfl_xor_sync(0xffffffffu, ep, 2);
        if ((lane & 3) == 0) sent[row][wid] = ep;
    }
    __syncthreads();

    if (tid < 32) {
        float e4 = sent[tid][0] + sent[tid][1] + sent[tid][2] + sent[tid][3];
        outEnt[(size_t)(r0 + tid) * NITER + t] = -e4;
    }

    __nv_bfloat16* XthN = g_Xth[(t + 1) & 1];
    __nv_bfloat16* XtlN = g_Xtl[(t + 1) & 1];
    for (int idx = tid; idx < NCP * 16; idx += 128) {
        int cc = idx >> 4;
        int pos = (idx & 15) * 2;
        uint32_t p0 = sp[cc * 32 + pos];
        uint32_t p1 = sp[cc * 32 + pos + 1];
        uint32_t hi = (p0 & 0xFFFFu) | (p1 << 16);
        uint32_t lo = (p0 >> 16) | (p1 & 0xFFFF0000u);
        *(uint32_t*)(XthN + (size_t)cc * BSZ + r0 + pos) = hi;
        *(uint32_t*)(XtlN + (size_t)cc * BSZ + r0 + pos) = lo;
    }
}

// ==================== launch ====================
extern "C" void kernel_launch(void* const* d_in, const int* in_sizes, int n_in,
                              void* d_out, int out_size) {
    (void)in_sizes; (void)n_in; (void)out_size;
    const float* emb = (const float*)d_in[0];
    const int* labels = (const int*)d_in[1];
    float* out = (float*)d_out;
    float* outXs = out;                                 // [B, NC, NITER]
    float* outEnt = out + (size_t)BSZ * NC * NITER;     // [B, NITER]

    cudaFuncSetAttribute(k_iter_mma, cudaFuncAttributeMaxDynamicSharedMemorySize, DSMEM);
    cudaFuncSetAttribute(k_gemmA_mma, cudaFuncAttributeMaxDynamicSharedMemorySize, A_DSMEM);

    k_normalize<<<BSZ, 256>>>(emb);
    k_gemmA_mma<<<GT * (GT + 1) / 2, 256, A_DSMEM>>>();
    k_mean1<<<1024, 256>>>();
    k_mean2<<<1, 1024>>>();
    k_splitA<<<(int)(((size_t)BSZ * BSZ) / (8 * 256)), 256>>>();
    k_initX<<<BSZ, NCP>>>(labels);
    for (int t = 0; t < NITER; t++)
        k_iter_mma<<<BSZ / 32, 128, DSMEM>>>(t, outXs, outEnt);
}

// round 6
// speedup vs baseline: 8.0129x; 1.1160x over previous
#include <cuda_runtime.h>
#include <cuda_bf16.h>
#include <cstdint>

#define BSZ   4096
#define DIM   1024
#define NC    100
#define NCP   128
#define NITER 30
#define NLAB  2048
#define GT    32
#define NTRI  (GT * (GT + 1) / 2)     // 528 upper-tri tiles

// ---- scratch (static device globals; no runtime allocation) ----
__device__ __nv_bfloat16 g_neh[(size_t)BSZ * DIM];
__device__ __nv_bfloat16 g_nel[(size_t)BSZ * DIM];
__device__ float g_A[(size_t)BSZ * BSZ];
__device__ __nv_bfloat16 g_Ah[(size_t)BSZ * BSZ];
__device__ __nv_bfloat16 g_Al[(size_t)BSZ * BSZ];
__device__ float g_Xf[2][(size_t)BSZ * NCP];
__device__ __nv_bfloat16 g_Xth[2][(size_t)NCP * BSZ];
__device__ __nv_bfloat16 g_Xtl[2][(size_t)NCP * BSZ];
__device__ float g_part[1024];
__device__ float g_mean;

// ==================== asm helpers (base PTX) ====================
__device__ __forceinline__ uint32_t smem_u32(const void* p) {
    uint32_t a;
    asm("{ .reg .u64 t; cvta.to.shared.u64 t, %1; cvt.u32.u64 %0, t; }" : "=r"(a) : "l"(p));
    return a;
}
__device__ __forceinline__ void cp16(uint32_t dst, const void* src) {
    asm volatile("cp.async.cg.shared.global [%0], [%1], 16;"
                 :: "r"(dst), "l"(__cvta_generic_to_global(src)) : "memory");
}
__device__ __forceinline__ void cp_commit() {
    asm volatile("cp.async.commit_group;" ::: "memory");
}
template <int N>
__device__ __forceinline__ void cp_wait() {
    asm volatile("cp.async.wait_group %0;" :: "n"(N) : "memory");
}
__device__ __forceinline__ void ldmx4(uint32_t* r, uint32_t addr) {
    asm volatile("ldmatrix.sync.aligned.m8n8.x4.shared.b16 {%0,%1,%2,%3}, [%4];"
                 : "=r"(r[0]), "=r"(r[1]), "=r"(r[2]), "=r"(r[3]) : "r"(addr));
}
__device__ __forceinline__ void mma16816(float* d, const uint32_t* a, const uint32_t* b) {
    asm volatile("mma.sync.aligned.m16n8k16.row.col.f32.bf16.bf16.f32 "
                 "{%0,%1,%2,%3}, {%4,%5,%6,%7}, {%8,%9}, {%0,%1,%2,%3};"
                 : "+f"(d[0]), "+f"(d[1]), "+f"(d[2]), "+f"(d[3])
                 : "r"(a[0]), "r"(a[1]), "r"(a[2]), "r"(a[3]), "r"(b[0]), "r"(b[1]));
}
__device__ __forceinline__ void barg(int id) {
    asm volatile("bar.sync %0, 128;" :: "r"(id) : "memory");
}
__device__ __forceinline__ uint32_t swz(uint32_t row, uint32_t gran16) {
    return (row * 128u + gran16 * 16u) ^ ((row & 7u) << 4);
}

// ==================== K1: row-normalize -> bf16 hi/lo ====================
__global__ void k_normalize(const float* __restrict__ emb) {
    int r = blockIdx.x;
    int tid = threadIdx.x;
    float4 x = ((const float4*)(emb + (size_t)r * DIM))[tid];
    float ss = x.x * x.x + x.y * x.y + x.z * x.z + x.w * x.w;
    __shared__ float red[8];
#pragma unroll
    for (int o = 16; o; o >>= 1) ss += __shfl_xor_sync(0xffffffffu, ss, o);
    if ((tid & 31) == 0) red[tid >> 5] = ss;
    __syncthreads();
    float tot = red[0] + red[1] + red[2] + red[3] + red[4] + red[5] + red[6] + red[7];
    float sc = 1.f / (sqrtf(tot) + 1e-12f);
    float v[4] = {x.x * sc, x.y * sc, x.z * sc, x.w * sc};
    uint32_t hh[2], ll[2];
#pragma unroll
    for (int j = 0; j < 2; j++) {
        __nv_bfloat16 h0 = __float2bfloat16(v[2 * j]);
        __nv_bfloat16 h1 = __float2bfloat16(v[2 * j + 1]);
        __nv_bfloat16 l0 = __float2bfloat16(v[2 * j] - __bfloat162float(h0));
        __nv_bfloat16 l1 = __float2bfloat16(v[2 * j + 1] - __bfloat162float(h1));
        hh[j] = (uint32_t)__bfloat16_as_ushort(h0) | ((uint32_t)__bfloat16_as_ushort(h1) << 16);
        ll[j] = (uint32_t)__bfloat16_as_ushort(l0) | ((uint32_t)__bfloat16_as_ushort(l1) << 16);
    }
    ((uint2*)(g_neh + (size_t)r * DIM))[tid] = make_uint2(hh[0], hh[1]);
    ((uint2*)(g_nel + (size_t)r * DIM))[tid] = make_uint2(ll[0], ll[1]);
}

// ==================== K2: A = clamp(ne @ ne^T) via HMMA split-3 + fused tile-sum ====================
#define AKC 64
#define ACH (DIM / AKC)
#define A_AH 0
#define A_AL 16384
#define A_BH 32768
#define A_BL 49152
#define A_STAGE 65536
#define A_DSMEM (1024 + 2 * A_STAGE)

__global__ void __launch_bounds__(256, 1) k_gemmA_mma() {
    extern __shared__ char dsm[];
    __shared__ float sred[8];
    uint32_t raw = smem_u32(dsm);
    uint32_t sbase = ((raw + 1023u) & ~1023u);
    char* sgen = dsm + (sbase - raw);
    uint32_t stg = sbase;

    int tid = threadIdx.x, wid = tid >> 5, lane = tid & 31;
    int wm = wid >> 2, wn = wid & 3;

    int b = blockIdx.x;
    int ti = 0;
    while ((ti + 1) * GT - ti * (ti + 1) / 2 <= b) ti++;
    int tj = ti + (b - (ti * GT - ti * (ti - 1) / 2));
    int r0 = ti * 128, c0 = tj * 128;

    auto load_stage = [&](int k0, int buf) {
        uint32_t bu = stg + buf * A_STAGE;
        int g = tid & 7, rb = tid >> 3;
#pragma unroll
        for (int j = 0; j < 4; j++) {
            int row = rb + 32 * j;
            size_t ga = (size_t)(r0 + row) * DIM + k0 + g * 8;
            size_t gb = (size_t)(c0 + row) * DIM + k0 + g * 8;
            uint32_t so = swz(row, g);
            cp16(bu + A_AH + so, g_neh + ga);
            cp16(bu + A_AL + so, g_nel + ga);
            cp16(bu + A_BH + so, g_neh + gb);
            cp16(bu + A_BL + so, g_nel + gb);
        }
        cp_commit();
    };

    float acc[4][4][4];
#pragma unroll
    for (int q = 0; q < 4; q++)
#pragma unroll
        for (int nt = 0; nt < 4; nt++)
#pragma unroll
            for (int e = 0; e < 4; e++) acc[q][nt][e] = 0.f;

    load_stage(0, 0);
    load_stage(AKC, 1);

    for (int c = 0; c < ACH; c++) {
        if (c == ACH - 1) cp_wait<0>(); else cp_wait<1>();
        __syncthreads();
        uint32_t bu = stg + (c & 1) * A_STAGE;
#pragma unroll
        for (int ks = 0; ks < 4; ks++) {
            uint32_t ah[4][4], al[4][4];
#pragma unroll
            for (int q = 0; q < 4; q++) {
                uint32_t off = swz(wm * 64 + q * 16 + (lane & 15), ks * 2 + (lane >> 4));
                ldmx4(ah[q], bu + A_AH + off);
                ldmx4(al[q], bu + A_AL + off);
            }
            uint32_t bh[4][2], bl[4][2];
#pragma unroll
            for (int p = 0; p < 2; p++) {
                uint32_t row = wn * 32 + p * 16 + (lane & 7) + ((lane >> 4) & 1) * 8;
                uint32_t off = swz(row, ks * 2 + ((lane >> 3) & 1));
                uint32_t t4[4];
                ldmx4(t4, bu + A_BH + off);
                bh[2 * p][0] = t4[0]; bh[2 * p][1] = t4[1];
                bh[2 * p + 1][0] = t4[2]; bh[2 * p + 1][1] = t4[3];
                ldmx4(t4, bu + A_BL + off);
                bl[2 * p][0] = t4[0]; bl[2 * p][1] = t4[1];
                bl[2 * p + 1][0] = t4[2]; bl[2 * p + 1][1] = t4[3];
            }
#pragma unroll
            for (int q = 0; q < 4; q++)
#pragma unroll
                for (int nt = 0; nt < 4; nt++) {
                    mma16816(acc[q][nt], ah[q], bh[nt]);
                    mma16816(acc[q][nt], ah[q], bl[nt]);
                    mma16816(acc[q][nt], al[q], bh[nt]);
                }
        }
        __syncthreads();
        if (c + 2 < ACH) load_stage((c + 2) * AKC, c & 1);
    }

    // ---- epilogue: stage C, clamp/diag, direct + mirror writes, fused tile sum ----
    float* Cs = (float*)sgen;
#pragma unroll
    for (int q = 0; q < 4; q++) {
        int row = wm * 64 + q * 16 + (lane >> 2);
        int col = wn * 32 + (lane & 3) * 2;
#pragma unroll
        for (int nt = 0; nt < 4; nt++) {
            Cs[row * 130 + col + nt * 8]           = acc[q][nt][0];
            Cs[row * 130 + col + nt * 8 + 1]       = acc[q][nt][1];
            Cs[(row + 8) * 130 + col + nt * 8]     = acc[q][nt][2];
            Cs[(row + 8) * 130 + col + nt * 8 + 1] = acc[q][nt][3];
        }
    }
    __syncthreads();
    float s = 0.f;
    for (int idx = tid; idx < 128 * 128; idx += 256) {
        int i = idx >> 7, j = idx & 127;
        int gi = r0 + i, gj = c0 + j;
        float v = Cs[i * 130 + j];
        v = (gi == gj) ? 0.f : fminf(fmaxf(v, 0.f), 1.f);
        s += v;
        g_A[(size_t)gi * BSZ + gj] = v;
    }
    if (ti != tj) {
        for (int idx = tid; idx < 128 * 128; idx += 256) {
            int i = idx >> 7, j = idx & 127;
            float v = Cs[j * 130 + i];
            v = fminf(fmaxf(v, 0.f), 1.f);
            g_A[(size_t)(c0 + i) * BSZ + (r0 + j)] = v;
        }
    }
#pragma unroll
    for (int o = 16; o; o >>= 1) s += __shfl_xor_sync(0xffffffffu, s, o);
    if (lane == 0) sred[wid] = s;
    __syncthreads();
    if (tid == 0) {
        float t = 0.f;
#pragma unroll
        for (int i = 0; i < 8; i++) t += sred[i];
        g_part[b] = t * ((ti == tj) ? 1.f : 2.f);
    }
}

// ==================== K3: final mean reduce (528 partials, fixed tree) ====================
__global__ void k_mean2() {
    __shared__ float red[1024];
    int tid = threadIdx.x;
    red[tid] = (tid < NTRI) ? g_part[tid] : 0.f;
    __syncthreads();
    for (int o = 512; o; o >>= 1) {
        if (tid < o) red[tid] += red[tid + o];
        __syncthreads();
    }
    if (tid == 0) g_mean = red[0] * (1.f / ((float)BSZ * (float)BSZ));
}

// ==================== K5: threshold + bf16 hi/lo split of A ====================
__global__ void k_splitA() {
    float m = g_mean;
    size_t i = ((size_t)blockIdx.x * 256 + threadIdx.x) * 8;
    float4 v0 = *(const float4*)(g_A + i);
    float4 v1 = *(const float4*)(g_A + i + 4);
    float f[8] = {v0.x, v0.y, v0.z, v0.w, v1.x, v1.y, v1.z, v1.w};
    uint32_t hw[4], lw[4];
#pragma unroll
    for (int j = 0; j < 4; j++) {
        float f0 = (f[2 * j]     < m) ? 0.f : f[2 * j];
        float f1 = (f[2 * j + 1] < m) ? 0.f : f[2 * j + 1];
        __nv_bfloat16 h0 = __float2bfloat16(f0), h1 = __float2bfloat16(f1);
        __nv_bfloat16 l0 = __float2bfloat16(f0 - __bfloat162float(h0));
        __nv_bfloat16 l1 = __float2bfloat16(f1 - __bfloat162float(h1));
        hw[j] = (uint32_t)__bfloat16_as_ushort(h0) | ((uint32_t)__bfloat16_as_ushort(h1) << 16);
        lw[j] = (uint32_t)__bfloat16_as_ushort(l0) | ((uint32_t)__bfloat16_as_ushort(l1) << 16);
    }
    *(uint4*)(g_Ah + i) = make_uint4(hw[0], hw[1], hw[2], hw[3]);
    *(uint4*)(g_Al + i) = make_uint4(lw[0], lw[1], lw[2], lw[3]);
}

// ==================== K6: init X ====================
__global__ void k_initX(const int* __restrict__ labels) {
    int r = blockIdx.x, c = threadIdx.x;
    float v;
    if (r < NLAB) v = (c == labels[r]) ? 1.f : 0.f;
    else          v = (c < NC) ? 0.01f : 0.f;
    g_Xf[0][(size_t)r * NCP + c] = v;
    __nv_bfloat16 h = __float2bfloat16(v);
    g_Xth[0][(size_t)c * BSZ + r] = h;
    g_Xtl[0][(size_t)c * BSZ + r] = __float2bfloat16(v - __bfloat162float(h));
}

// ==================== K7: HMMA replicator iteration, warp K-split (2 groups) ====================
#define KC 64
#define NCHUNK (BSZ / KC)
#define AH_OFF 0
#define AL_OFF 4096
#define XH_OFF 8192
#define XL_OFF 24576
#define STAGE_B 40960
#define DSMEM (1024 + 4 * STAGE_B)

__global__ void __launch_bounds__(256, 1) k_iter_mma(int t, float* __restrict__ outXs,
                                                     float* __restrict__ outEnt) {
    extern __shared__ char dsm[];
    __shared__ uint32_t sp[NCP * 32];
    __shared__ float srow[32][4];
    __shared__ float sent[32][4];

    uint32_t raw = smem_u32(dsm);
    uint32_t sbase = (raw + 1023u) & ~1023u;
    char* sgen = dsm + (sbase - raw);

    int tid = threadIdx.x;
    int wid = tid >> 5, lane = tid & 31;
    int g = wid >> 2, wn = wid & 3;
    int ltid = tid & 127;
    int r0 = blockIdx.x * 32;

    const __nv_bfloat16* __restrict__ Ah = g_Ah;
    const __nv_bfloat16* __restrict__ Al = g_Al;
    const __nv_bfloat16* __restrict__ Xth = g_Xth[t & 1];
    const __nv_bfloat16* __restrict__ Xtl = g_Xtl[t & 1];

    // group g handles chunks c = 2*i + g, double-buffered in buffers 2g, 2g+1
    auto load_stage = [&](int c, int buf) {
        uint32_t bu = sbase + buf * STAGE_B;
        int k0 = c * KC;
        int gg = ltid & 7;
        int rbase = ltid >> 3;
#pragma unroll
        for (int j = 0; j < 2; j++) {
            int row = rbase + 16 * j;
            size_t ga = (size_t)(r0 + row) * BSZ + k0 + gg * 8;
            cp16(bu + AH_OFF + swz(row, gg), Ah + ga);
            cp16(bu + AL_OFF + swz(row, gg), Al + ga);
        }
#pragma unroll
        for (int j = 0; j < 8; j++) {
            int row = rbase + 16 * j;
            size_t gx = (size_t)row * BSZ + k0 + gg * 8;
            cp16(bu + XH_OFF + swz(row, gg), Xth + gx);
            cp16(bu + XL_OFF + swz(row, gg), Xtl + gx);
        }
        cp_commit();
    };

    float acc[2][4][4];
#pragma unroll
    for (int q = 0; q < 2; q++)
#pragma unroll
        for (int nt = 0; nt < 4; nt++)
#pragma unroll
            for (int e = 0; e < 4; e++) acc[q][nt][e] = 0.f;

    load_stage(g, 2 * g);
    load_stage(2 + g, 2 * g + 1);

    for (int i = 0; i < NCHUNK / 2; i++) {
        if (i == NCHUNK / 2 - 1) cp_wait<0>(); else cp_wait<1>();
        barg(1 + g);
        uint32_t bu = sbase + (2 * g + (i & 1)) * STAGE_B;
#pragma unroll
        for (int ks = 0; ks < 4; ks++) {
            uint32_t ah[2][4], al2[2][4];
#pragma unroll
            for (int q = 0; q < 2; q++) {
                uint32_t off = swz(q * 16 + (lane & 15), ks * 2 + (lane >> 4));
                ldmx4(ah[q],  bu + AH_OFF + off);
                ldmx4(al2[q], bu + AL_OFF + off);
            }
            uint32_t bh[4][2], bl[4][2];
#pragma unroll
            for (int p = 0; p < 2; p++) {
                uint32_t row = wn * 32 + p * 16 + (lane & 7) + ((lane >> 4) & 1) * 8;
                uint32_t off = swz(row, ks * 2 + ((lane >> 3) & 1));
                uint32_t t4[4];
                ldmx4(t4, bu + XH_OFF + off);
                bh[2 * p][0] = t4[0]; bh[2 * p][1] = t4[1];
                bh[2 * p + 1][0] = t4[2]; bh[2 * p + 1][1] = t4[3];
                ldmx4(t4, bu + XL_OFF + off);
                bl[2 * p][0] = t4[0]; bl[2 * p][1] = t4[1];
                bl[2 * p + 1][0] = t4[2]; bl[2 * p + 1][1] = t4[3];
            }
#pragma unroll
            for (int q = 0; q < 2; q++)
#pragma unroll
                for (int nt = 0; nt < 4; nt++) {
                    mma16816(acc[q][nt], ah[q], bh[nt]);
                    mma16816(acc[q][nt], ah[q], bl[nt]);
                    mma16816(acc[q][nt], al2[q], bh[nt]);
                }
        }
        barg(1 + g);
        if (i + 2 < NCHUNK / 2) load_stage(2 * (i + 2) + g, 2 * g + (i & 1));
    }

    // ---- merge group 1 accumulators into group 0 via smem ----
    __syncthreads();
    float* mrg = (float*)sgen;                 // 32 x 128 fp32 = 16 KB (reuses stages)
    if (g == 1) {
#pragma unroll
        for (int q = 0; q < 2; q++)
#pragma unroll
            for (int nt = 0; nt < 4; nt++) {
                int row = q * 16 + (lane >> 2);
                int col = wn * 32 + nt * 8 + 2 * (lane & 3);
                mrg[row * NCP + col]           = acc[q][nt][0];
                mrg[row * NCP + col + 1]       = acc[q][nt][1];
                mrg[(row + 8) * NCP + col]     = acc[q][nt][2];
                mrg[(row + 8) * NCP + col + 1] = acc[q][nt][3];
            }
    }
    __syncthreads();

    const float* __restrict__ Xin  = g_Xf[t & 1];
    float* __restrict__ Xout = g_Xf[(t + 1) & 1];

    if (g == 0) {
#pragma unroll
        for (int q = 0; q < 2; q++)
#pragma unroll
            for (int nt = 0; nt < 4; nt++) {
                int row = q * 16 + (lane >> 2);
                int col = wn * 32 + nt * 8 + 2 * (lane & 3);
                acc[q][nt][0] += mrg[row * NCP + col];
                acc[q][nt][1] += mrg[row * NCP + col + 1];
                acc[q][nt][2] += mrg[(row + 8) * NCP + col];
                acc[q][nt][3] += mrg[(row + 8) * NCP + col + 1];
            }

        float xv[4][4][2];
        int cb = wn * 32 + 2 * (lane & 3);
#pragma unroll
        for (int rr = 0; rr < 4; rr++) {
            int row = (rr >> 1) * 16 + (rr & 1) * 8 + (lane >> 2);
            int gr = r0 + row;
            float s = 0.f;
#pragma unroll
            for (int nt = 0; nt < 4; nt++) {
                float2 x2 = *(const float2*)(Xin + (size_t)gr * NCP + cb + nt * 8);
                xv[rr][nt][0] = x2.x; xv[rr][nt][1] = x2.y;
                int q = rr >> 1, hb = (rr & 1) * 2;
#pragma unroll
                for (int e = 0; e < 2; e++) {
                    int cc = cb + nt * 8 + e;
                    if (cc < NC) s += xv[rr][nt][e] * acc[q][nt][hb + e];
                }
            }
            s += __shfl_xor_sync(0xffffffffu, s, 1);
            s += __shfl_xor_sync(0xffffffffu, s, 2);
            if ((lane & 3) == 0) srow[row][wn] = s;
        }
        barg(1);   // group-0 barrier

#pragma unroll
        for (int rr = 0; rr < 4; rr++) {
            int row = (rr >> 1) * 16 + (rr & 1) * 8 + (lane >> 2);
            int gr = r0 + row;
            float tot = srow[row][0] + srow[row][1] + srow[row][2] + srow[row][3];
            float inv = 1.f / (tot + 1e-8f);
            float ep = 0.f;
            int q = rr >> 1, hb = (rr & 1) * 2;
#pragma unroll
            for (int nt = 0; nt < 4; nt++) {
                float xo2[2];
#pragma unroll
                for (int e = 0; e < 2; e++) {
                    int cc = cb + nt * 8 + e;
                    float xvv = xv[rr][nt][e];
                    float num = (cc < NC) ? xvv * acc[q][nt][hb + e] : 0.f;
                    float dv = num * inv;
                    float xo = xvv + dv;
                    if (cc < NC) {
                        ep += dv * __logf(dv + 1e-20f);
                        outXs[(size_t)gr * (NC * NITER) + (size_t)cc * NITER + t] = dv;
                    }
                    xo2[e] = xo;
                    __nv_bfloat16 h = __float2bfloat16(xo);
                    __nv_bfloat16 l = __float2bfloat16(xo - __bfloat162float(h));
                    sp[cc * 32 + row] = (uint32_t)__bfloat16_as_ushort(h) |
                                        ((uint32_t)__bfloat16_as_ushort(l) << 16);
                }
                *(float2*)(Xout + (size_t)gr * NCP + cb + nt * 8) = make_float2(xo2[0], xo2[1]);
            }
            ep += __shfl_xor_sync(0xffffffffu, ep, 1);
            ep += __shfl_xor_sync(0xffffffffu, ep, 2);
            if ((lane & 3) == 0) sent[row][wn] = ep;
        }
    }
    __syncthreads();

    if (tid < 32) {
        float e4 = sent[tid][0] + sent[tid][1] + sent[tid][2] + sent[tid][3];
        outEnt[(size_t)(r0 + tid) * NITER + t] = -e4;
    }

    __nv_bfloat16* XthN = g_Xth[(t + 1) & 1];
    __nv_bfloat16* XtlN = g_Xtl[(t + 1) & 1];
    for (int idx = tid; idx < NCP * 16; idx += 256) {
        int cc = idx >> 4;
        int pos = (idx & 15) * 2;
        uint32_t p0 = sp[cc * 32 + pos];
        uint32_t p1 = sp[cc * 32 + pos + 1];
        uint32_t hi = (p0 & 0xFFFFu) | (p1 << 16);
        uint32_t lo = (p0 >> 16) | (p1 & 0xFFFF0000u);
        *(uint32_t*)(XthN + (size_t)cc * BSZ + r0 + pos) = hi;
        *(uint32_t*)(XtlN + (size_t)cc * BSZ + r0 + pos) = lo;
    }
}

// ==================== launch ====================
extern "C" void kernel_launch(void* const* d_in, const int* in_sizes, int n_in,
                              void* d_out, int out_size) {
    (void)in_sizes; (void)n_in; (void)out_size;
    const float* emb = (const float*)d_in[0];
    const int* labels = (const int*)d_in[1];
    float* out = (float*)d_out;
    float* outXs = out;
    float* outEnt = out + (size_t)BSZ * NC * NITER;

    cudaFuncSetAttribute(k_iter_mma, cudaFuncAttributeMaxDynamicSharedMemorySize, DSMEM);
    cudaFuncSetAttribute(k_gemmA_mma, cudaFuncAttributeMaxDynamicSharedMemorySize, A_DSMEM);

    k_normalize<<<BSZ, 256>>>(emb);
    k_gemmA_mma<<<NTRI, 256, A_DSMEM>>>();
    k_mean2<<<1, 1024>>>();
    k_splitA<<<(int)(((size_t)BSZ * BSZ) / (8 * 256)), 256>>>();
    k_initX<<<BSZ, NCP>>>(labels);
    for (int t = 0; t < NITER; t++)
        k_iter_mma<<<BSZ / 32, 256, DSMEM>>>(t, outXs, outEnt);
}

// round 7
// speedup vs baseline: 8.2733x; 1.0325x over previous
#include <cuda_runtime.h>
#include <cuda_bf16.h>
#include <cstdint>

#define BSZ   4096
#define DIM   1024
#define NC    100
#define NCP   128
#define NITER 30
#define NLAB  2048
#define GT    32
#define NTRI  (GT * (GT + 1) / 2)
#define NSPL  4                        // K-splits for iteration GEMM

// ---- scratch (static device globals) ----
__device__ __nv_bfloat16 g_neh[(size_t)BSZ * DIM];
__device__ __nv_bfloat16 g_nel[(size_t)BSZ * DIM];
__device__ float g_A[(size_t)BSZ * BSZ];
__device__ __nv_bfloat16 g_Ah[(size_t)BSZ * BSZ];
__device__ __nv_bfloat16 g_Al[(size_t)BSZ * BSZ];
__device__ float g_Xf[2][(size_t)BSZ * NCP];
__device__ __nv_bfloat16 g_Xth[2][(size_t)NCP * BSZ];
__device__ __nv_bfloat16 g_Xtl[2][(size_t)NCP * BSZ];
__device__ float g_D[NSPL][(size_t)BSZ * NCP];      // per-K-split partials (8 MB)
__device__ float g_part[1024];
__device__ float g_mean;

// ==================== asm helpers (base PTX) ====================
__device__ __forceinline__ uint32_t smem_u32(const void* p) {
    uint32_t a;
    asm("{ .reg .u64 t; cvta.to.shared.u64 t, %1; cvt.u32.u64 %0, t; }" : "=r"(a) : "l"(p));
    return a;
}
__device__ __forceinline__ void cp16(uint32_t dst, const void* src) {
    asm volatile("cp.async.cg.shared.global [%0], [%1], 16;"
                 :: "r"(dst), "l"(__cvta_generic_to_global(src)) : "memory");
}
__device__ __forceinline__ void cp_commit() {
    asm volatile("cp.async.commit_group;" ::: "memory");
}
template <int N>
__device__ __forceinline__ void cp_wait() {
    asm volatile("cp.async.wait_group %0;" :: "n"(N) : "memory");
}
__device__ __forceinline__ void ldmx4(uint32_t* r, uint32_t addr) {
    asm volatile("ldmatrix.sync.aligned.m8n8.x4.shared.b16 {%0,%1,%2,%3}, [%4];"
                 : "=r"(r[0]), "=r"(r[1]), "=r"(r[2]), "=r"(r[3]) : "r"(addr));
}
__device__ __forceinline__ void mma16816(float* d, const uint32_t* a, const uint32_t* b) {
    asm volatile("mma.sync.aligned.m16n8k16.row.col.f32.bf16.bf16.f32 "
                 "{%0,%1,%2,%3}, {%4,%5,%6,%7}, {%8,%9}, {%0,%1,%2,%3};"
                 : "+f"(d[0]), "+f"(d[1]), "+f"(d[2]), "+f"(d[3])
                 : "r"(a[0]), "r"(a[1]), "r"(a[2]), "r"(a[3]), "r"(b[0]), "r"(b[1]));
}
__device__ __forceinline__ uint32_t swz(uint32_t row, uint32_t gran16) {
    return (row * 128u + gran16 * 16u) ^ ((row & 7u) << 4);
}

// ==================== K1: row-normalize -> bf16 hi/lo ====================
__global__ void k_normalize(const float* __restrict__ emb) {
    int r = blockIdx.x;
    int tid = threadIdx.x;
    float4 x = ((const float4*)(emb + (size_t)r * DIM))[tid];
    float ss = x.x * x.x + x.y * x.y + x.z * x.z + x.w * x.w;
    __shared__ float red[8];
#pragma unroll
    for (int o = 16; o; o >>= 1) ss += __shfl_xor_sync(0xffffffffu, ss, o);
    if ((tid & 31) == 0) red[tid >> 5] = ss;
    __syncthreads();
    float tot = red[0] + red[1] + red[2] + red[3] + red[4] + red[5] + red[6] + red[7];
    float sc = 1.f / (sqrtf(tot) + 1e-12f);
    float v[4] = {x.x * sc, x.y * sc, x.z * sc, x.w * sc};
    uint32_t hh[2], ll[2];
#pragma unroll
    for (int j = 0; j < 2; j++) {
        __nv_bfloat16 h0 = __float2bfloat16(v[2 * j]);
        __nv_bfloat16 h1 = __float2bfloat16(v[2 * j + 1]);
        __nv_bfloat16 l0 = __float2bfloat16(v[2 * j] - __bfloat162float(h0));
        __nv_bfloat16 l1 = __float2bfloat16(v[2 * j + 1] - __bfloat162float(h1));
        hh[j] = (uint32_t)__bfloat16_as_ushort(h0) | ((uint32_t)__bfloat16_as_ushort(h1) << 16);
        ll[j] = (uint32_t)__bfloat16_as_ushort(l0) | ((uint32_t)__bfloat16_as_ushort(l1) << 16);
    }
    ((uint2*)(g_neh + (size_t)r * DIM))[tid] = make_uint2(hh[0], hh[1]);
    ((uint2*)(g_nel + (size_t)r * DIM))[tid] = make_uint2(ll[0], ll[1]);
}

// ==================== K2: A = clamp(ne @ ne^T) via HMMA split-3 + fused tile-sum ====================
#define AKC 64
#define ACH (DIM / AKC)
#define A_AH 0
#define A_AL 16384
#define A_BH 32768
#define A_BL 49152
#define A_STAGE 65536
#define A_DSMEM (1024 + 2 * A_STAGE)

__global__ void __launch_bounds__(256, 1) k_gemmA_mma() {
    extern __shared__ char dsm[];
    __shared__ float sred[8];
    uint32_t raw = smem_u32(dsm);
    uint32_t sbase = ((raw + 1023u) & ~1023u);
    char* sgen = dsm + (sbase - raw);
    uint32_t stg = sbase;

    int tid = threadIdx.x, wid = tid >> 5, lane = tid & 31;
    int wm = wid >> 2, wn = wid & 3;

    int b = blockIdx.x;
    int ti = 0;
    while ((ti + 1) * GT - ti * (ti + 1) / 2 <= b) ti++;
    int tj = ti + (b - (ti * GT - ti * (ti - 1) / 2));
    int r0 = ti * 128, c0 = tj * 128;

    auto load_stage = [&](int k0, int buf) {
        uint32_t bu = stg + buf * A_STAGE;
        int g = tid & 7, rb = tid >> 3;
#pragma unroll
        for (int j = 0; j < 4; j++) {
            int row = rb + 32 * j;
            size_t ga = (size_t)(r0 + row) * DIM + k0 + g * 8;
            size_t gb = (size_t)(c0 + row) * DIM + k0 + g * 8;
            uint32_t so = swz(row, g);
            cp16(bu + A_AH + so, g_neh + ga);
            cp16(bu + A_AL + so, g_nel + ga);
            cp16(bu + A_BH + so, g_neh + gb);
            cp16(bu + A_BL + so, g_nel + gb);
        }
        cp_commit();
    };

    float acc[4][4][4];
#pragma unroll
    for (int q = 0; q < 4; q++)
#pragma unroll
        for (int nt = 0; nt < 4; nt++)
#pragma unroll
            for (int e = 0; e < 4; e++) acc[q][nt][e] = 0.f;

    load_stage(0, 0);
    load_stage(AKC, 1);

    for (int c = 0; c < ACH; c++) {
        if (c == ACH - 1) cp_wait<0>(); else cp_wait<1>();
        __syncthreads();
        uint32_t bu = stg + (c & 1) * A_STAGE;
#pragma unroll
        for (int ks = 0; ks < 4; ks++) {
            uint32_t ah[4][4], al[4][4];
#pragma unroll
            for (int q = 0; q < 4; q++) {
                uint32_t off = swz(wm * 64 + q * 16 + (lane & 15), ks * 2 + (lane >> 4));
                ldmx4(ah[q], bu + A_AH + off);
                ldmx4(al[q], bu + A_AL + off);
            }
            uint32_t bh[4][2], bl[4][2];
#pragma unroll
            for (int p = 0; p < 2; p++) {
                uint32_t row = wn * 32 + p * 16 + (lane & 7) + ((lane >> 4) & 1) * 8;
                uint32_t off = swz(row, ks * 2 + ((lane >> 3) & 1));
                uint32_t t4[4];
                ldmx4(t4, bu + A_BH + off);
                bh[2 * p][0] = t4[0]; bh[2 * p][1] = t4[1];
                bh[2 * p + 1][0] = t4[2]; bh[2 * p + 1][1] = t4[3];
                ldmx4(t4, bu + A_BL + off);
                bl[2 * p][0] = t4[0]; bl[2 * p][1] = t4[1];
                bl[2 * p + 1][0] = t4[2]; bl[2 * p + 1][1] = t4[3];
            }
#pragma unroll
            for (int q = 0; q < 4; q++)
#pragma unroll
                for (int nt = 0; nt < 4; nt++) {
                    mma16816(acc[q][nt], ah[q], bh[nt]);
                    mma16816(acc[q][nt], ah[q], bl[nt]);
                    mma16816(acc[q][nt], al[q], bh[nt]);
                }
        }
        __syncthreads();
        if (c + 2 < ACH) load_stage((c + 2) * AKC, c & 1);
    }

    float* Cs = (float*)sgen;
#pragma unroll
    for (int q = 0; q < 4; q++) {
        int row = wm * 64 + q * 16 + (lane >> 2);
        int col = wn * 32 + (lane & 3) * 2;
#pragma unroll
        for (int nt = 0; nt < 4; nt++) {
            Cs[row * 130 + col + nt * 8]           = acc[q][nt][0];
            Cs[row * 130 + col + nt * 8 + 1]       = acc[q][nt][1];
            Cs[(row + 8) * 130 + col + nt * 8]     = acc[q][nt][2];
            Cs[(row + 8) * 130 + col + nt * 8 + 1] = acc[q][nt][3];
        }
    }
    __syncthreads();
    float s = 0.f;
    for (int idx = tid; idx < 128 * 128; idx += 256) {
        int i = idx >> 7, j = idx & 127;
        int gi = r0 + i, gj = c0 + j;
        float v = Cs[i * 130 + j];
        v = (gi == gj) ? 0.f : fminf(fmaxf(v, 0.f), 1.f);
        s += v;
        g_A[(size_t)gi * BSZ + gj] = v;
    }
    if (ti != tj) {
        for (int idx = tid; idx < 128 * 128; idx += 256) {
            int i = idx >> 7, j = idx & 127;
            float v = Cs[j * 130 + i];
            v = fminf(fmaxf(v, 0.f), 1.f);
            g_A[(size_t)(c0 + i) * BSZ + (r0 + j)] = v;
        }
    }
#pragma unroll
    for (int o = 16; o; o >>= 1) s += __shfl_xor_sync(0xffffffffu, s, o);
    if (lane == 0) sred[wid] = s;
    __syncthreads();
    if (tid == 0) {
        float t = 0.f;
#pragma unroll
        for (int i = 0; i < 8; i++) t += sred[i];
        g_part[b] = t * ((ti == tj) ? 1.f : 2.f);
    }
}

// ==================== K3: final mean reduce ====================
__global__ void k_mean2() {
    __shared__ float red[1024];
    int tid = threadIdx.x;
    red[tid] = (tid < NTRI) ? g_part[tid] : 0.f;
    __syncthreads();
    for (int o = 512; o; o >>= 1) {
        if (tid < o) red[tid] += red[tid + o];
        __syncthreads();
    }
    if (tid == 0) g_mean = red[0] * (1.f / ((float)BSZ * (float)BSZ));
}

// ==================== K5: threshold + bf16 hi/lo split of A ====================
__global__ void k_splitA() {
    float m = g_mean;
    size_t i = ((size_t)blockIdx.x * 256 + threadIdx.x) * 8;
    float4 v0 = *(const float4*)(g_A + i);
    float4 v1 = *(const float4*)(g_A + i + 4);
    float f[8] = {v0.x, v0.y, v0.z, v0.w, v1.x, v1.y, v1.z, v1.w};
    uint32_t hw[4], lw[4];
#pragma unroll
    for (int j = 0; j < 4; j++) {
        float f0 = (f[2 * j]     < m) ? 0.f : f[2 * j];
        float f1 = (f[2 * j + 1] < m) ? 0.f : f[2 * j + 1];
        __nv_bfloat16 h0 = __float2bfloat16(f0), h1 = __float2bfloat16(f1);
        __nv_bfloat16 l0 = __float2bfloat16(f0 - __bfloat162float(h0));
        __nv_bfloat16 l1 = __float2bfloat16(f1 - __bfloat162float(h1));
        hw[j] = (uint32_t)__bfloat16_as_ushort(h0) | ((uint32_t)__bfloat16_as_ushort(h1) << 16);
        lw[j] = (uint32_t)__bfloat16_as_ushort(l0) | ((uint32_t)__bfloat16_as_ushort(l1) << 16);
    }
    *(uint4*)(g_Ah + i) = make_uint4(hw[0], hw[1], hw[2], hw[3]);
    *(uint4*)(g_Al + i) = make_uint4(lw[0], lw[1], lw[2], lw[3]);
}

// ==================== K6: init X ====================
__global__ void k_initX(const int* __restrict__ labels) {
    int r = blockIdx.x, c = threadIdx.x;
    float v;
    if (r < NLAB) v = (c == labels[r]) ? 1.f : 0.f;
    else          v = (c < NC) ? 0.01f : 0.f;
    g_Xf[0][(size_t)r * NCP + c] = v;
    __nv_bfloat16 h = __float2bfloat16(v);
    g_Xth[0][(size_t)c * BSZ + r] = h;
    g_Xtl[0][(size_t)c * BSZ + r] = __float2bfloat16(v - __bfloat162float(h));
}

// ==================== K7: iteration GEMM (128x128 tiles, K-split x4) ====================
__global__ void __launch_bounds__(256, 1) k_iter_gemm(int t) {
    extern __shared__ char dsm[];
    uint32_t raw = smem_u32(dsm);
    uint32_t sbase = ((raw + 1023u) & ~1023u);
    uint32_t stg = sbase;

    int tid = threadIdx.x, wid = tid >> 5, lane = tid & 31;
    int wm = wid >> 2, wn = wid & 3;
    int ks = blockIdx.x >> 5, mt = blockIdx.x & 31;
    int r0 = mt * 128;
    int kb = ks * (BSZ / NSPL);

    const __nv_bfloat16* __restrict__ Ah = g_Ah;
    const __nv_bfloat16* __restrict__ Al = g_Al;
    const __nv_bfloat16* __restrict__ Xth = g_Xth[t & 1];
    const __nv_bfloat16* __restrict__ Xtl = g_Xtl[t & 1];

    auto load_stage = [&](int k0, int buf) {
        uint32_t bu = stg + buf * A_STAGE;
        int g = tid & 7, rb = tid >> 3;
#pragma unroll
        for (int j = 0; j < 4; j++) {
            int row = rb + 32 * j;
            size_t ga = (size_t)(r0 + row) * BSZ + kb + k0 + g * 8;
            size_t gx = (size_t)row * BSZ + kb + k0 + g * 8;
            uint32_t so = swz(row, g);
            cp16(bu + A_AH + so, Ah + ga);
            cp16(bu + A_AL + so, Al + ga);
            cp16(bu + A_BH + so, Xth + gx);
            cp16(bu + A_BL + so, Xtl + gx);
        }
        cp_commit();
    };

    float acc[4][4][4];
#pragma unroll
    for (int q = 0; q < 4; q++)
#pragma unroll
        for (int nt = 0; nt < 4; nt++)
#pragma unroll
            for (int e = 0; e < 4; e++) acc[q][nt][e] = 0.f;

    load_stage(0, 0);
    load_stage(AKC, 1);

    const int KCH = (BSZ / NSPL) / AKC;        // 16 chunks
    for (int c = 0; c < KCH; c++) {
        if (c == KCH - 1) cp_wait<0>(); else cp_wait<1>();
        __syncthreads();
        uint32_t bu = stg + (c & 1) * A_STAGE;
#pragma unroll
        for (int kq = 0; kq < 4; kq++) {
            uint32_t ah[4][4], al[4][4];
#pragma unroll
            for (int q = 0; q < 4; q++) {
                uint32_t off = swz(wm * 64 + q * 16 + (lane & 15), kq * 2 + (lane >> 4));
                ldmx4(ah[q], bu + A_AH + off);
                ldmx4(al[q], bu + A_AL + off);
            }
            uint32_t bh[4][2], bl[4][2];
#pragma unroll
            for (int p = 0; p < 2; p++) {
                uint32_t row = wn * 32 + p * 16 + (lane & 7) + ((lane >> 4) & 1) * 8;
                uint32_t off = swz(row, kq * 2 + ((lane >> 3) & 1));
                uint32_t t4[4];
                ldmx4(t4, bu + A_BH + off);
                bh[2 * p][0] = t4[0]; bh[2 * p][1] = t4[1];
                bh[2 * p + 1][0] = t4[2]; bh[2 * p + 1][1] = t4[3];
                ldmx4(t4, bu + A_BL + off);
                bl[2 * p][0] = t4[0]; bl[2 * p][1] = t4[1];
                bl[2 * p + 1][0] = t4[2]; bl[2 * p + 1][1] = t4[3];
            }
#pragma unroll
            for (int q = 0; q < 4; q++)
#pragma unroll
                for (int nt = 0; nt < 4; nt++) {
                    mma16816(acc[q][nt], ah[q], bh[nt]);
                    mma16816(acc[q][nt], ah[q], bl[nt]);
                    mma16816(acc[q][nt], al[q], bh[nt]);
                }
        }
        __syncthreads();
        if (c + 2 < KCH) load_stage((c + 2) * AKC, c & 1);
    }

    // write fp32 partials (deterministic per-ks buffers)
    float* P = g_D[ks];
#pragma unroll
    for (int q = 0; q < 4; q++) {
        int row = wm * 64 + q * 16 + (lane >> 2);
        int col = wn * 32 + 2 * (lane & 3);
#pragma unroll
        for (int nt = 0; nt < 4; nt++) {
            *(float2*)(P + (size_t)(r0 + row) * NCP + col + nt * 8) =
                make_float2(acc[q][nt][0], acc[q][nt][1]);
            *(float2*)(P + (size_t)(r0 + row + 8) * NCP + col + nt * 8) =
                make_float2(acc[q][nt][2], acc[q][nt][3]);
        }
    }
}

// ==================== K8: epilogue (sum partials, div/entropy/outputs/X update) ====================
__global__ void __launch_bounds__(256) k_epi(int t, float* __restrict__ outXs,
                                             float* __restrict__ outEnt) {
    __shared__ uint32_t sp[NCP * 32];
    int tid = threadIdx.x;
    int row = tid >> 3, part = tid & 7;
    int r0 = blockIdx.x * 32;
    int gr = r0 + row;
    const float* __restrict__ Xin = g_Xf[t & 1];
    float* __restrict__ Xout = g_Xf[(t + 1) & 1];

    float dd[16], xv[16], num[16];
    float s = 0.f;
    size_t base = (size_t)gr * NCP + part * 16;
#pragma unroll
    for (int v = 0; v < 4; v++) {
        size_t off = base + v * 4;
        float4 p0 = *(const float4*)(g_D[0] + off);
        float4 p1 = *(const float4*)(g_D[1] + off);
        float4 p2 = *(const float4*)(g_D[2] + off);
        float4 p3 = *(const float4*)(g_D[3] + off);
        dd[v * 4 + 0] = (p0.x + p1.x) + (p2.x + p3.x);
        dd[v * 4 + 1] = (p0.y + p1.y) + (p2.y + p3.y);
        dd[v * 4 + 2] = (p0.z + p1.z) + (p2.z + p3.z);
        dd[v * 4 + 3] = (p0.w + p1.w) + (p2.w + p3.w);
        float4 x4 = *(const float4*)(Xin + off);
        xv[v * 4 + 0] = x4.x; xv[v * 4 + 1] = x4.y;
        xv[v * 4 + 2] = x4.z; xv[v * 4 + 3] = x4.w;
    }
#pragma unroll
    for (int i = 0; i < 16; i++) {
        int cc = part * 16 + i;
        num[i] = (cc < NC) ? xv[i] * dd[i] : 0.f;
        s += num[i];
    }
    s += __shfl_xor_sync(0xffffffffu, s, 1);
    s += __shfl_xor_sync(0xffffffffu, s, 2);
    s += __shfl_xor_sync(0xffffffffu, s, 4);
    float inv = 1.f / (s + 1e-8f);

    float ep = 0.f;
#pragma unroll
    for (int v = 0; v < 4; v++) {
        float xo4[4];
#pragma unroll
        for (int i = 0; i < 4; i++) {
            int idx = v * 4 + i;
            int cc = part * 16 + idx;
            float dv = num[idx] * inv;
            float xo = xv[idx] + dv;
            if (cc < NC) {
                ep += dv * __logf(dv + 1e-20f);
                outXs[(size_t)gr * (NC * NITER) + (size_t)cc * NITER + t] = dv;
            }
            xo4[i] = xo;
            __nv_bfloat16 h = __float2bfloat16(xo);
            __nv_bfloat16 l = __float2bfloat16(xo - __bfloat162float(h));
            sp[cc * 32 + row] = (uint32_t)__bfloat16_as_ushort(h) |
                                ((uint32_t)__bfloat16_as_ushort(l) << 16);
        }
        *(float4*)(Xout + base + v * 4) = make_float4(xo4[0], xo4[1], xo4[2], xo4[3]);
    }
    ep += __shfl_xor_sync(0xffffffffu, ep, 1);
    ep += __shfl_xor_sync(0xffffffffu, ep, 2);
    ep += __shfl_xor_sync(0xffffffffu, ep, 4);
    if (part == 0) outEnt[(size_t)gr * NITER + t] = -ep;
    __syncthreads();

    __nv_bfloat16* XthN = g_Xth[(t + 1) & 1];
    __nv_bfloat16* XtlN = g_Xtl[(t + 1) & 1];
    for (int idx = tid; idx < NCP * 16; idx += 256) {
        int cc = idx >> 4;
        int pos = (idx & 15) * 2;
        uint32_t p0 = sp[cc * 32 + pos];
        uint32_t p1 = sp[cc * 32 + pos + 1];
        uint32_t hi = (p0 & 0xFFFFu) | (p1 << 16);
        uint32_t lo = (p0 >> 16) | (p1 & 0xFFFF0000u);
        *(uint32_t*)(XthN + (size_t)cc * BSZ + r0 + pos) = hi;
        *(uint32_t*)(XtlN + (size_t)cc * BSZ + r0 + pos) = lo;
    }
}

// ==================== launch ====================
extern "C" void kernel_launch(void* const* d_in, const int* in_sizes, int n_in,
                              void* d_out, int out_size) {
    (void)in_sizes; (void)n_in; (void)out_size;
    const float* emb = (const float*)d_in[0];
    const int* labels = (const int*)d_in[1];
    float* out = (float*)d_out;
    float* outXs = out;
    float* outEnt = out + (size_t)BSZ * NC * NITER;

    cudaFuncSetAttribute(k_gemmA_mma, cudaFuncAttributeMaxDynamicSharedMemorySize, A_DSMEM);
    cudaFuncSetAttribute(k_iter_gemm, cudaFuncAttributeMaxDynamicSharedMemorySize, A_DSMEM);

    k_normalize<<<BSZ, 256>>>(emb);
    k_gemmA_mma<<<NTRI, 256, A_DSMEM>>>();
    k_mean2<<<1, 1024>>>();
    k_splitA<<<(int)(((size_t)BSZ * BSZ) / (8 * 256)), 256>>>();
    k_initX<<<BSZ, NCP>>>(labels);
    for (int t = 0; t < NITER; t++) {
        k_iter_gemm<<<NSPL * 32, 256, A_DSMEM>>>(t);
        k_epi<<<BSZ / 32, 256>>>(t, outXs, outEnt);
    }
}

// round 8
// speedup vs baseline: 13.8113x; 1.6694x over previous
#include <cuda_runtime.h>
#include <cuda_bf16.h>
#include <cuda_fp16.h>
#include <cstdint>

#define BSZ   4096
#define DIM   1024
#define NC    100
#define NCP   128
#define NITER 30
#define NLAB  2048
#define GT    32
#define NTRI  (GT * (GT + 1) / 2)
#define NSPL  8                        // K-splits for iteration GEMM

// ---- scratch (static device globals) ----
__device__ __nv_bfloat16 g_neh[(size_t)BSZ * DIM];
__device__ __nv_bfloat16 g_nel[(size_t)BSZ * DIM];
__device__ float g_A[(size_t)BSZ * BSZ];
__device__ __half g_Af16[(size_t)BSZ * BSZ];         // thresholded A, fp16 (32 MB)
__device__ float g_Xf[2][(size_t)BSZ * NCP];
__device__ __half g_Xt16[2][(size_t)NCP * BSZ];      // X^T fp16 [N=128][K=4096]
__device__ float g_D[NSPL][(size_t)BSZ * NCP];       // per-K-split partials (16 MB)
__device__ float g_part[1024];
__device__ float g_mean;

// ==================== asm helpers (base PTX) ====================
__device__ __forceinline__ uint32_t smem_u32(const void* p) {
    uint32_t a;
    asm("{ .reg .u64 t; cvta.to.shared.u64 t, %1; cvt.u32.u64 %0, t; }" : "=r"(a) : "l"(p));
    return a;
}
__device__ __forceinline__ void cp16(uint32_t dst, const void* src) {
    asm volatile("cp.async.cg.shared.global [%0], [%1], 16;"
                 :: "r"(dst), "l"(__cvta_generic_to_global(src)) : "memory");
}
__device__ __forceinline__ void cp_commit() {
    asm volatile("cp.async.commit_group;" ::: "memory");
}
template <int N>
__device__ __forceinline__ void cp_wait() {
    asm volatile("cp.async.wait_group %0;" :: "n"(N) : "memory");
}
__device__ __forceinline__ void ldmx4(uint32_t* r, uint32_t addr) {
    asm volatile("ldmatrix.sync.aligned.m8n8.x4.shared.b16 {%0,%1,%2,%3}, [%4];"
                 : "=r"(r[0]), "=r"(r[1]), "=r"(r[2]), "=r"(r[3]) : "r"(addr));
}
__device__ __forceinline__ void mma16816_bf(float* d, const uint32_t* a, const uint32_t* b) {
    asm volatile("mma.sync.aligned.m16n8k16.row.col.f32.bf16.bf16.f32 "
                 "{%0,%1,%2,%3}, {%4,%5,%6,%7}, {%8,%9}, {%0,%1,%2,%3};"
                 : "+f"(d[0]), "+f"(d[1]), "+f"(d[2]), "+f"(d[3])
                 : "r"(a[0]), "r"(a[1]), "r"(a[2]), "r"(a[3]), "r"(b[0]), "r"(b[1]));
}
__device__ __forceinline__ void mma16816_hf(float* d, const uint32_t* a, const uint32_t* b) {
    asm volatile("mma.sync.aligned.m16n8k16.row.col.f32.f16.f16.f32 "
                 "{%0,%1,%2,%3}, {%4,%5,%6,%7}, {%8,%9}, {%0,%1,%2,%3};"
                 : "+f"(d[0]), "+f"(d[1]), "+f"(d[2]), "+f"(d[3])
                 : "r"(a[0]), "r"(a[1]), "r"(a[2]), "r"(a[3]), "r"(b[0]), "r"(b[1]));
}
__device__ __forceinline__ uint32_t swz(uint32_t row, uint32_t gran16) {
    return (row * 128u + gran16 * 16u) ^ ((row & 7u) << 4);
}

// ==================== K1: row-normalize -> bf16 hi/lo ====================
__global__ void k_normalize(const float* __restrict__ emb) {
    int r = blockIdx.x;
    int tid = threadIdx.x;
    float4 x = ((const float4*)(emb + (size_t)r * DIM))[tid];
    float ss = x.x * x.x + x.y * x.y + x.z * x.z + x.w * x.w;
    __shared__ float red[8];
#pragma unroll
    for (int o = 16; o; o >>= 1) ss += __shfl_xor_sync(0xffffffffu, ss, o);
    if ((tid & 31) == 0) red[tid >> 5] = ss;
    __syncthreads();
    float tot = red[0] + red[1] + red[2] + red[3] + red[4] + red[5] + red[6] + red[7];
    float sc = 1.f / (sqrtf(tot) + 1e-12f);
    float v[4] = {x.x * sc, x.y * sc, x.z * sc, x.w * sc};
    uint32_t hh[2], ll[2];
#pragma unroll
    for (int j = 0; j < 2; j++) {
        __nv_bfloat16 h0 = __float2bfloat16(v[2 * j]);
        __nv_bfloat16 h1 = __float2bfloat16(v[2 * j + 1]);
        __nv_bfloat16 l0 = __float2bfloat16(v[2 * j] - __bfloat162float(h0));
        __nv_bfloat16 l1 = __float2bfloat16(v[2 * j + 1] - __bfloat162float(h1));
        hh[j] = (uint32_t)__bfloat16_as_ushort(h0) | ((uint32_t)__bfloat16_as_ushort(h1) << 16);
        ll[j] = (uint32_t)__bfloat16_as_ushort(l0) | ((uint32_t)__bfloat16_as_ushort(l1) << 16);
    }
    ((uint2*)(g_neh + (size_t)r * DIM))[tid] = make_uint2(hh[0], hh[1]);
    ((uint2*)(g_nel + (size_t)r * DIM))[tid] = make_uint2(ll[0], ll[1]);
}

// ==================== K2: A = clamp(ne @ ne^T) via HMMA split-3 + fused tile-sum ====================
#define AKC 64
#define ACH (DIM / AKC)
#define A_AH 0
#define A_AL 16384
#define A_BH 32768
#define A_BL 49152
#define A_STAGE 65536
#define A_DSMEM (1024 + 2 * A_STAGE)

__global__ void __launch_bounds__(256, 1) k_gemmA_mma() {
    extern __shared__ char dsm[];
    __shared__ float sred[8];
    uint32_t raw = smem_u32(dsm);
    uint32_t sbase = ((raw + 1023u) & ~1023u);
    char* sgen = dsm + (sbase - raw);
    uint32_t stg = sbase;

    int tid = threadIdx.x, wid = tid >> 5, lane = tid & 31;
    int wm = wid >> 2, wn = wid & 3;

    int b = blockIdx.x;
    int ti = 0;
    while ((ti + 1) * GT - ti * (ti + 1) / 2 <= b) ti++;
    int tj = ti + (b - (ti * GT - ti * (ti - 1) / 2));
    int r0 = ti * 128, c0 = tj * 128;

    auto load_stage = [&](int k0, int buf) {
        uint32_t bu = stg + buf * A_STAGE;
        int g = tid & 7, rb = tid >> 3;
#pragma unroll
        for (int j = 0; j < 4; j++) {
            int row = rb + 32 * j;
            size_t ga = (size_t)(r0 + row) * DIM + k0 + g * 8;
            size_t gb = (size_t)(c0 + row) * DIM + k0 + g * 8;
            uint32_t so = swz(row, g);
            cp16(bu + A_AH + so, g_neh + ga);
            cp16(bu + A_AL + so, g_nel + ga);
            cp16(bu + A_BH + so, g_neh + gb);
            cp16(bu + A_BL + so, g_nel + gb);
        }
        cp_commit();
    };

    float acc[4][4][4];
#pragma unroll
    for (int q = 0; q < 4; q++)
#pragma unroll
        for (int nt = 0; nt < 4; nt++)
#pragma unroll
            for (int e = 0; e < 4; e++) acc[q][nt][e] = 0.f;

    load_stage(0, 0);
    load_stage(AKC, 1);

    for (int c = 0; c < ACH; c++) {
        if (c == ACH - 1) cp_wait<0>(); else cp_wait<1>();
        __syncthreads();
        uint32_t bu = stg + (c & 1) * A_STAGE;
#pragma unroll
        for (int ks = 0; ks < 4; ks++) {
            uint32_t ah[4][4], al[4][4];
#pragma unroll
            for (int q = 0; q < 4; q++) {
                uint32_t off = swz(wm * 64 + q * 16 + (lane & 15), ks * 2 + (lane >> 4));
                ldmx4(ah[q], bu + A_AH + off);
                ldmx4(al[q], bu + A_AL + off);
            }
            uint32_t bh[4][2], bl[4][2];
#pragma unroll
            for (int p = 0; p < 2; p++) {
                uint32_t row = wn * 32 + p * 16 + (lane & 7) + ((lane >> 4) & 1) * 8;
                uint32_t off = swz(row, ks * 2 + ((lane >> 3) & 1));
                uint32_t t4[4];
                ldmx4(t4, bu + A_BH + off);
                bh[2 * p][0] = t4[0]; bh[2 * p][1] = t4[1];
                bh[2 * p + 1][0] = t4[2]; bh[2 * p + 1][1] = t4[3];
                ldmx4(t4, bu + A_BL + off);
                bl[2 * p][0] = t4[0]; bl[2 * p][1] = t4[1];
                bl[2 * p + 1][0] = t4[2]; bl[2 * p + 1][1] = t4[3];
            }
#pragma unroll
            for (int q = 0; q < 4; q++)
#pragma unroll
                for (int nt = 0; nt < 4; nt++) {
                    mma16816_bf(acc[q][nt], ah[q], bh[nt]);
                    mma16816_bf(acc[q][nt], ah[q], bl[nt]);
                    mma16816_bf(acc[q][nt], al[q], bh[nt]);
                }
        }
        __syncthreads();
        if (c + 2 < ACH) load_stage((c + 2) * AKC, c & 1);
    }

    float* Cs = (float*)sgen;
#pragma unroll
    for (int q = 0; q < 4; q++) {
        int row = wm * 64 + q * 16 + (lane >> 2);
        int col = wn * 32 + (lane & 3) * 2;
#pragma unroll
        for (int nt = 0; nt < 4; nt++) {
            Cs[row * 130 + col + nt * 8]           = acc[q][nt][0];
            Cs[row * 130 + col + nt * 8 + 1]       = acc[q][nt][1];
            Cs[(row + 8) * 130 + col + nt * 8]     = acc[q][nt][2];
            Cs[(row + 8) * 130 + col + nt * 8 + 1] = acc[q][nt][3];
        }
    }
    __syncthreads();
    float s = 0.f;
    for (int idx = tid; idx < 128 * 128; idx += 256) {
        int i = idx >> 7, j = idx & 127;
        int gi = r0 + i, gj = c0 + j;
        float v = Cs[i * 130 + j];
        v = (gi == gj) ? 0.f : fminf(fmaxf(v, 0.f), 1.f);
        s += v;
        g_A[(size_t)gi * BSZ + gj] = v;
    }
    if (ti != tj) {
        for (int idx = tid; idx < 128 * 128; idx += 256) {
            int i = idx >> 7, j = idx & 127;
            float v = Cs[j * 130 + i];
            v = fminf(fmaxf(v, 0.f), 1.f);
            g_A[(size_t)(c0 + i) * BSZ + (r0 + j)] = v;
        }
    }
#pragma unroll
    for (int o = 16; o; o >>= 1) s += __shfl_xor_sync(0xffffffffu, s, o);
    if (lane == 0) sred[wid] = s;
    __syncthreads();
    if (tid == 0) {
        float t = 0.f;
#pragma unroll
        for (int i = 0; i < 8; i++) t += sred[i];
        g_part[b] = t * ((ti == tj) ? 1.f : 2.f);
    }
}

// ==================== K3: final mean reduce ====================
__global__ void k_mean2() {
    __shared__ float red[1024];
    int tid = threadIdx.x;
    red[tid] = (tid < NTRI) ? g_part[tid] : 0.f;
    __syncthreads();
    for (int o = 512; o; o >>= 1) {
        if (tid < o) red[tid] += red[tid + o];
        __syncthreads();
    }
    if (tid == 0) g_mean = red[0] * (1.f / ((float)BSZ * (float)BSZ));
}

// ==================== K5: threshold + fp16 cast of A ====================
__global__ void k_splitA() {
    float m = g_mean;
    size_t i = ((size_t)blockIdx.x * 256 + threadIdx.x) * 8;
    float4 v0 = *(const float4*)(g_A + i);
    float4 v1 = *(const float4*)(g_A + i + 4);
    float f[8] = {v0.x, v0.y, v0.z, v0.w, v1.x, v1.y, v1.z, v1.w};
    uint32_t hw[4];
#pragma unroll
    for (int j = 0; j < 4; j++) {
        float f0 = (f[2 * j]     < m) ? 0.f : f[2 * j];
        float f1 = (f[2 * j + 1] < m) ? 0.f : f[2 * j + 1];
        __half h0 = __float2half_rn(f0), h1 = __float2half_rn(f1);
        hw[j] = (uint32_t)__half_as_ushort(h0) | ((uint32_t)__half_as_ushort(h1) << 16);
    }
    *(uint4*)(g_Af16 + i) = make_uint4(hw[0], hw[1], hw[2], hw[3]);
}

// ==================== K6: init X ====================
__global__ void k_initX(const int* __restrict__ labels) {
    int r = blockIdx.x, c = threadIdx.x;
    float v;
    if (r < NLAB) v = (c == labels[r]) ? 1.f : 0.f;
    else          v = (c < NC) ? 0.01f : 0.f;
    g_Xf[0][(size_t)r * NCP + c] = v;
    g_Xt16[0][(size_t)c * BSZ + r] = __float2half_rn(v);
}

// ==================== K7: iteration GEMM (128x128 tiles, fp16 single-term, K-split x8) ====================
#define I_A 0
#define I_X 16384
#define I_STAGE 32768
#define I_DSMEM (1024 + 2 * I_STAGE)

__global__ void __launch_bounds__(256, 2) k_iter_gemm(int t) {
    extern __shared__ char dsm[];
    uint32_t raw = smem_u32(dsm);
    uint32_t sbase = ((raw + 1023u) & ~1023u);
    uint32_t stg = sbase;

    int tid = threadIdx.x, wid = tid >> 5, lane = tid & 31;
    int wm = wid >> 2, wn = wid & 3;
    int ks = blockIdx.x >> 5, mt = blockIdx.x & 31;
    int r0 = mt * 128;
    int kb = ks * (BSZ / NSPL);

    const __half* __restrict__ Af = g_Af16;
    const __half* __restrict__ Xt = g_Xt16[t & 1];

    auto load_stage = [&](int k0, int buf) {
        uint32_t bu = stg + buf * I_STAGE;
        int g = tid & 7, rb = tid >> 3;
#pragma unroll
        for (int j = 0; j < 4; j++) {
            int row = rb + 32 * j;
            size_t ga = (size_t)(r0 + row) * BSZ + kb + k0 + g * 8;
            size_t gx = (size_t)row * BSZ + kb + k0 + g * 8;
            uint32_t so = swz(row, g);
            cp16(bu + I_A + so, Af + ga);
            cp16(bu + I_X + so, Xt + gx);
        }
        cp_commit();
    };

    float acc[4][4][4];
#pragma unroll
    for (int q = 0; q < 4; q++)
#pragma unroll
        for (int nt = 0; nt < 4; nt++)
#pragma unroll
            for (int e = 0; e < 4; e++) acc[q][nt][e] = 0.f;

    load_stage(0, 0);
    load_stage(AKC, 1);

    const int KCH = (BSZ / NSPL) / AKC;        // 8 chunks
    for (int c = 0; c < KCH; c++) {
        if (c == KCH - 1) cp_wait<0>(); else cp_wait<1>();
        __syncthreads();
        uint32_t bu = stg + (c & 1) * I_STAGE;
#pragma unroll
        for (int kq = 0; kq < 4; kq++) {
            uint32_t a[4][4];
#pragma unroll
            for (int q = 0; q < 4; q++) {
                uint32_t off = swz(wm * 64 + q * 16 + (lane & 15), kq * 2 + (lane >> 4));
                ldmx4(a[q], bu + I_A + off);
            }
            uint32_t bm[4][2];
#pragma unroll
            for (int p = 0; p < 2; p++) {
                uint32_t row = wn * 32 + p * 16 + (lane & 7) + ((lane >> 4) & 1) * 8;
                uint32_t off = swz(row, kq * 2 + ((lane >> 3) & 1));
                uint32_t t4[4];
                ldmx4(t4, bu + I_X + off);
                bm[2 * p][0] = t4[0]; bm[2 * p][1] = t4[1];
                bm[2 * p + 1][0] = t4[2]; bm[2 * p + 1][1] = t4[3];
            }
#pragma unroll
            for (int q = 0; q < 4; q++)
#pragma unroll
                for (int nt = 0; nt < 4; nt++)
                    mma16816_hf(acc[q][nt], a[q], bm[nt]);
        }
        __syncthreads();
        if (c + 2 < KCH) load_stage((c + 2) * AKC, c & 1);
    }

    float* P = g_D[ks];
#pragma unroll
    for (int q = 0; q < 4; q++) {
        int row = wm * 64 + q * 16 + (lane >> 2);
        int col = wn * 32 + 2 * (lane & 3);
#pragma unroll
        for (int nt = 0; nt < 4; nt++) {
            *(float2*)(P + (size_t)(r0 + row) * NCP + col + nt * 8) =
                make_float2(acc[q][nt][0], acc[q][nt][1]);
            *(float2*)(P + (size_t)(r0 + row + 8) * NCP + col + nt * 8) =
                make_float2(acc[q][nt][2], acc[q][nt][3]);
        }
    }
}

// ==================== K8: epilogue (sum partials, div/entropy/outputs/X update) ====================
__global__ void __launch_bounds__(256) k_epi(int t, float* __restrict__ outXs,
                                             float* __restrict__ outEnt) {
    __shared__ __half sp16[NCP * 32];
    int tid = threadIdx.x;
    int row = tid >> 3, part = tid & 7;
    int r0 = blockIdx.x * 32;
    int gr = r0 + row;
    const float* __restrict__ Xin = g_Xf[t & 1];
    float* __restrict__ Xout = g_Xf[(t + 1) & 1];

    float dd[16], xv[16], num[16];
    float s = 0.f;
    size_t base = (size_t)gr * NCP + part * 16;
#pragma unroll
    for (int v = 0; v < 4; v++) {
        size_t off = base + v * 4;
        float4 acc4 = *(const float4*)(g_D[0] + off);
#pragma unroll
        for (int p = 1; p < NSPL; p++) {
            float4 pp = *(const float4*)(g_D[p] + off);
            acc4.x += pp.x; acc4.y += pp.y; acc4.z += pp.z; acc4.w += pp.w;
        }
        dd[v * 4 + 0] = acc4.x; dd[v * 4 + 1] = acc4.y;
        dd[v * 4 + 2] = acc4.z; dd[v * 4 + 3] = acc4.w;
        float4 x4 = *(const float4*)(Xin + off);
        xv[v * 4 + 0] = x4.x; xv[v * 4 + 1] = x4.y;
        xv[v * 4 + 2] = x4.z; xv[v * 4 + 3] = x4.w;
    }
#pragma unroll
    for (int i = 0; i < 16; i++) {
        int cc = part * 16 + i;
        num[i] = (cc < NC) ? xv[i] * dd[i] : 0.f;
        s += num[i];
    }
    s += __shfl_xor_sync(0xffffffffu, s, 1);
    s += __shfl_xor_sync(0xffffffffu, s, 2);
    s += __shfl_xor_sync(0xffffffffu, s, 4);
    float inv = 1.f / (s + 1e-8f);

    float ep = 0.f;
#pragma unroll
    for (int v = 0; v < 4; v++) {
        float xo4[4];
#pragma unroll
        for (int i = 0; i < 4; i++) {
            int idx = v * 4 + i;
            int cc = part * 16 + idx;
            float dv = num[idx] * inv;
            float xo = xv[idx] + dv;
            if (cc < NC) {
                ep += dv * __logf(dv + 1e-20f);
                outXs[(size_t)gr * (NC * NITER) + (size_t)cc * NITER + t] = dv;
            }
            xo4[i] = xo;
            sp16[cc * 32 + row] = __float2half_rn(xo);
        }
        *(float4*)(Xout + base + v * 4) = make_float4(xo4[0], xo4[1], xo4[2], xo4[3]);
    }
    ep += __shfl_xor_sync(0xffffffffu, ep, 1);
    ep += __shfl_xor_sync(0xffffffffu, ep, 2);
    ep += __shfl_xor_sync(0xffffffffu, ep, 4);
    if (part == 0) outEnt[(size_t)gr * NITER + t] = -ep;
    __syncthreads();

    __half* XtN = g_Xt16[(t + 1) & 1];
    for (int idx = tid; idx < NCP * 16; idx += 256) {
        int cc = idx >> 4;
        int pos = (idx & 15) * 2;
        uint32_t h0 = (uint32_t)__half_as_ushort(sp16[cc * 32 + pos]);
        uint32_t h1 = (uint32_t)__half_as_ushort(sp16[cc * 32 + pos + 1]);
        *(uint32_t*)(XtN + (size_t)cc * BSZ + r0 + pos) = h0 | (h1 << 16);
    }
}

// ==================== launch ====================
extern "C" void kernel_launch(void* const* d_in, const int* in_sizes, int n_in,
                              void* d_out, int out_size) {
    (void)in_sizes; (void)n_in; (void)out_size;
    const float* emb = (const float*)d_in[0];
    const int* labels = (const int*)d_in[1];
    float* out = (float*)d_out;
    float* outXs = out;
    float* outEnt = out + (size_t)BSZ * NC * NITER;

    cudaFuncSetAttribute(k_gemmA_mma, cudaFuncAttributeMaxDynamicSharedMemorySize, A_DSMEM);
    cudaFuncSetAttribute(k_iter_gemm, cudaFuncAttributeMaxDynamicSharedMemorySize, I_DSMEM);

    k_normalize<<<BSZ, 256>>>(emb);
    k_gemmA_mma<<<NTRI, 256, A_DSMEM>>>();
    k_mean2<<<1, 1024>>>();
    k_splitA<<<(int)(((size_t)BSZ * BSZ) / (8 * 256)), 256>>>();
    k_initX<<<BSZ, NCP>>>(labels);
    for (int t = 0; t < NITER; t++) {
        k_iter_gemm<<<NSPL * 32, 256, I_DSMEM>>>(t);
        k_epi<<<BSZ / 32, 256>>>(t, outXs, outEnt);
    }
}